// round 14
// baseline (speedup 1.0000x reference)
#include <cuda_runtime.h>
#include <cuda_fp16.h>
#include <math.h>

#define BATCH 4
#define CHN 64
#define HW 65536        // 256*256
#define NDS 4096        // 64*64 downsampled pixels
#define THITA_F 1.0e-4f
#define OUT2OFF (BATCH * CHN * HW)

// ---------------- scratch (device globals) ----------------------------------
__device__ __half g_xdsh[BATCH * CHN * NDS];    // down4(x) f16 [b][c][n]
__device__ float  g_efd [BATCH * CHN * NDS];    // ef ds fp32 [b][c][n]
__device__ __half g_efdh[BATCH * CHN * NDS];    // ef ds f16
__device__ __half g_qh[BATCH * NDS * CHN];      // [b][n][d] f16
__device__ __half g_kh[BATCH * NDS * CHN];
__device__ __half g_vh[BATCH * NDS * CHN];
__device__ float  g_Op[2 * BATCH * CHN * NDS];  // split-KV partial O (unnormalized)
__device__ float  g_ml[2 * BATCH * 2 * NDS];    // split-KV per-row m and l
__device__ __half g_wh[64 * 200];               // conv0 weights f16 hi
__device__ __half g_wl[64 * 200];               // conv0 weights f16 lo

// ============================================================================
// mma / ldmatrix helpers
// ============================================================================
__device__ __forceinline__ void mma16816(float* d,
    unsigned a0, unsigned a1, unsigned a2, unsigned a3,
    unsigned b0, unsigned b1)
{
    asm volatile(
        "mma.sync.aligned.m16n8k16.row.col.f32.f16.f16.f32 "
        "{%0,%1,%2,%3}, {%4,%5,%6,%7}, {%8,%9}, {%0,%1,%2,%3};\n"
        : "+f"(d[0]), "+f"(d[1]), "+f"(d[2]), "+f"(d[3])
        : "r"(a0), "r"(a1), "r"(a2), "r"(a3), "r"(b0), "r"(b1));
}
// f16-accumulator variant
__device__ __forceinline__ void mma16816h(unsigned* d,
    unsigned a0, unsigned a1, unsigned a2, unsigned a3,
    unsigned b0, unsigned b1)
{
    asm volatile(
        "mma.sync.aligned.m16n8k16.row.col.f16.f16.f16.f16 "
        "{%0,%1}, {%2,%3,%4,%5}, {%6,%7}, {%0,%1};\n"
        : "+r"(d[0]), "+r"(d[1])
        : "r"(a0), "r"(a1), "r"(a2), "r"(a3), "r"(b0), "r"(b1));
}
__device__ __forceinline__ void ldm4(unsigned* r, unsigned a) {
    asm volatile("ldmatrix.sync.aligned.m8n8.x4.shared.b16 {%0,%1,%2,%3}, [%4];\n"
        : "=r"(r[0]), "=r"(r[1]), "=r"(r[2]), "=r"(r[3]) : "r"(a));
}
__device__ __forceinline__ void ldm4t(unsigned* r, unsigned a) {
    asm volatile("ldmatrix.sync.aligned.m8n8.x4.trans.shared.b16 {%0,%1,%2,%3}, [%4];\n"
        : "=r"(r[0]), "=r"(r[1]), "=r"(r[2]), "=r"(r[3]) : "r"(a));
}
__device__ __forceinline__ void cpasync16(unsigned dst, const void* src) {
    asm volatile("cp.async.cg.shared.global [%0], [%1], 16;\n"
        :: "r"(dst), "l"(src));
}
__device__ __forceinline__ unsigned hpack(__half a, __half b) {
    __half2 h = __halves2half2(a, b);
    return *(unsigned*)&h;
}
__device__ __forceinline__ unsigned packh2(float a, float b) {
    __half2 h = __floats2half2_rn(a, b);
    return *(unsigned*)&h;
}
__device__ __forceinline__ float sexp(float s, float c) {
    float t = fmaf(s, 12102203.16f, c);
    t = fmaxf(t, 0.0f);
    return __int_as_float(__float2int_rn(t));
}

// single-pass f16 GEMM
__device__ __forceinline__ void gemm1p(float acc[8][4], unsigned wb, int wstride,
                                       unsigned ab, int nks, int lane)
{
    int ln15 = lane & 15, hb8 = (lane >> 4) * 8;
    unsigned wl = wb + (ln15 * wstride + hb8) * 2;
    #pragma unroll
    for (int ks = 0; ks < nks; ks++) {
        unsigned al = ab + ((ks * 16 + ln15) * 72 + hb8) * 2;
        unsigned B[16], A[4];
        ldm4t(B,      al);
        ldm4t(B + 4,  al + 32);
        ldm4t(B + 8,  al + 64);
        ldm4t(B + 12, al + 96);
        ldm4(A, wl + ks * 32);
        #pragma unroll
        for (int nc = 0; nc < 8; nc++) {
            int ib = (nc >> 1) * 4 + (nc & 1) * 2;
            mma16816(acc[nc], A[0], A[1], A[2], A[3], B[ib], B[ib + 1]);
        }
    }
}

// 3-pass hi/lo GEMM (K=64)
__device__ __forceinline__ void gemm3p(float acc[8][4],
    unsigned wh, unsigned wlo, unsigned ah, unsigned alo, int lane)
{
    int ln15 = lane & 15, hb8 = (lane >> 4) * 8;
    unsigned wbh = wh  + (ln15 * 72 + hb8) * 2;
    unsigned wbl = wlo + (ln15 * 72 + hb8) * 2;
    #pragma unroll
    for (int ks = 0; ks < 4; ks++) {
        unsigned abh = ah  + ((ks * 16 + ln15) * 72 + hb8) * 2;
        unsigned abl = alo + ((ks * 16 + ln15) * 72 + hb8) * 2;
        unsigned Bh[16], Bl[16], Wf[4], Lf[4];
        ldm4t(Bh,      abh);
        ldm4t(Bh + 4,  abh + 32);
        ldm4t(Bh + 8,  abh + 64);
        ldm4t(Bh + 12, abh + 96);
        ldm4t(Bl,      abl);
        ldm4t(Bl + 4,  abl + 32);
        ldm4t(Bl + 8,  abl + 64);
        ldm4t(Bl + 12, abl + 96);
        ldm4(Wf, wbh + ks * 32);
        ldm4(Lf, wbl + ks * 32);
        #pragma unroll
        for (int nc = 0; nc < 8; nc++) {
            int ib = (nc >> 1) * 4 + (nc & 1) * 2;
            mma16816(acc[nc], Wf[0], Wf[1], Wf[2], Wf[3], Bh[ib], Bh[ib + 1]);
            mma16816(acc[nc], Wf[0], Wf[1], Wf[2], Wf[3], Bl[ib], Bl[ib + 1]);
            mma16816(acc[nc], Lf[0], Lf[1], Lf[2], Lf[3], Bh[ib], Bh[ib + 1]);
        }
    }
}

// ============================================================================
// K0: wconv
// ============================================================================
__global__ void wconv_kernel(const float* __restrict__ w)
{
    int i = blockIdx.x * 256 + threadIdx.x;
    if (i < 12288) {
        int o = i / 192, c = i - o * 192;
        float v = w[i];
        __half h = __float2half_rn(v);
        g_wh[o * 200 + c] = h;
        g_wl[o * 200 + c] = __float2half_rn(v - __half2float(h));
    }
}

// ============================================================================
// K1: prep (unchanged)
// ============================================================================
#define PREP_SMEM (64 * 200 * 2 + 192 * 72 * 2)

__global__ __launch_bounds__(128) void prep_kernel(
    const float* __restrict__ x1, const float* __restrict__ x2,
    const float* __restrict__ ev,
    const float* __restrict__ xw0, const float* __restrict__ xb0,
    const float* __restrict__ ew0, const float* __restrict__ eb0,
    const float* __restrict__ ew1, const float* __restrict__ eb1)
{
    extern __shared__ char smc[];
    unsigned smu = (unsigned)__cvta_generic_to_shared(smc);
    int t = threadIdx.x, lane = t & 31, w = t >> 5;
    int gid = lane >> 2, tig = lane & 3;
    int blk = blockIdx.x, b = blockIdx.y;
    int n0 = blk << 6;

    float acc[8][4];
    #pragma unroll
    for (int nc = 0; nc < 8; nc++)
        #pragma unroll
        for (int q = 0; q < 4; q++) acc[nc][q] = 0.0f;

    if (blockIdx.z == 0) {
        __half* W  = (__half*)smc;
        __half* Ac = (__half*)(smc + 64 * 200 * 2);
        for (int i = t; i < 12288; i += 128) {
            int o = i / 192, c = i - o * 192;
            W[o * 200 + c] = __float2half_rn(xw0[i]);
        }
        for (int i = t; i < 12288; i += 128) {
            int c = i >> 6, x = i & 63;
            const float* s = (c < 128) ? x1 + (size_t)(b * 128 + c) * HW
                                       : x2 + (size_t)(b * 64 + c - 128) * HW;
            Ac[c * 72 + x] = __float2half_rn(s[(blk << 10) + (x << 2)]);
        }
        __syncthreads();

        gemm1p(acc, smu + (w * 16) * 200 * 2, 200,
               smu + 64 * 200 * 2, 12, lane);

        int o = (w << 4) + gid;
        float b0 = __ldg(&xb0[o]), b1 = __ldg(&xb0[o + 8]);
        #pragma unroll
        for (int nc = 0; nc < 8; nc++) {
            int n = n0 + nc * 8 + tig * 2;
            *(__half2*)&g_xdsh[(size_t)(b * 64 + o) * NDS + n] =
                __floats2half2_rn(fmaxf(acc[nc][0] + b0, 0.0f),
                                  fmaxf(acc[nc][1] + b0, 0.0f));
            *(__half2*)&g_xdsh[(size_t)(b * 64 + o + 8) * NDS + n] =
                __floats2half2_rn(fmaxf(acc[nc][2] + b1, 0.0f),
                                  fmaxf(acc[nc][3] + b1, 0.0f));
        }
    } else {
        __half* Wh = (__half*)smc;
        __half* Wl = Wh + 64 * 72;
        __half* Ah = Wl + 64 * 72;
        __half* Al = Ah + 64 * 72;
        unsigned oWh = smu, oWl = smu + 9216, oAh = smu + 18432, oAl = smu + 27648;

        for (int i = t; i < 4096; i += 128) {
            float v = ew0[i];
            __half h = __float2half_rn(v);
            int o = i >> 6, c = i & 63;
            Wh[o * 72 + c] = h;
            Wl[o * 72 + c] = __float2half_rn(v - __half2float(h));
        }
        for (int i = t; i < 4096; i += 128) {
            int c = i >> 6, x = i & 63;
            float v = ev[(size_t)(b * 64 + c) * HW + (blk << 10) + (x << 2)];
            __half h = __float2half_rn(v);
            Ah[c * 72 + x] = h;
            Al[c * 72 + x] = __float2half_rn(v - __half2float(h));
        }
        __syncthreads();

        gemm3p(acc, oWh + (w * 16) * 144, oWl + (w * 16) * 144, oAh, oAl, lane);
        __syncthreads();

        {
            int o = (w << 4) + gid;
            float b0 = __ldg(&eb0[o]), b1 = __ldg(&eb0[o + 8]);
            #pragma unroll
            for (int nc = 0; nc < 8; nc++) {
                int px = nc * 8 + tig * 2;
                float t0 = fmaxf(acc[nc][0] + b0, 0.0f);
                float t1 = fmaxf(acc[nc][1] + b0, 0.0f);
                float t2 = fmaxf(acc[nc][2] + b1, 0.0f);
                float t3 = fmaxf(acc[nc][3] + b1, 0.0f);
                __half h0 = __float2half_rn(t0), h1 = __float2half_rn(t1);
                __half h2 = __float2half_rn(t2), h3 = __float2half_rn(t3);
                *(__half2*)&Ah[o * 72 + px] = __halves2half2(h0, h1);
                *(__half2*)&Al[o * 72 + px] = __floats2half2_rn(
                    t0 - __half2float(h0), t1 - __half2float(h1));
                *(__half2*)&Ah[(o + 8) * 72 + px] = __halves2half2(h2, h3);
                *(__half2*)&Al[(o + 8) * 72 + px] = __floats2half2_rn(
                    t2 - __half2float(h2), t3 - __half2float(h3));
            }
        }
        for (int i = t; i < 4096; i += 128) {
            float v = ew1[i];
            __half h = __float2half_rn(v);
            int o = i >> 6, c = i & 63;
            Wh[o * 72 + c] = h;
            Wl[o * 72 + c] = __float2half_rn(v - __half2float(h));
        }
        __syncthreads();

        #pragma unroll
        for (int nc = 0; nc < 8; nc++)
            #pragma unroll
            for (int q = 0; q < 4; q++) acc[nc][q] = 0.0f;
        gemm3p(acc, oWh + (w * 16) * 144, oWl + (w * 16) * 144, oAh, oAl, lane);

        int o = (w << 4) + gid;
        float b0 = __ldg(&eb1[o]), b1 = __ldg(&eb1[o + 8]);
        #pragma unroll
        for (int nc = 0; nc < 8; nc++) {
            int n = n0 + nc * 8 + tig * 2;
            float r0 = fmaxf(acc[nc][0] + b0, 0.0f);
            float r1 = fmaxf(acc[nc][1] + b0, 0.0f);
            float r2 = fmaxf(acc[nc][2] + b1, 0.0f);
            float r3 = fmaxf(acc[nc][3] + b1, 0.0f);
            *(float2*)&g_efd[(size_t)(b * 64 + o) * NDS + n]     = make_float2(r0, r1);
            *(float2*)&g_efd[(size_t)(b * 64 + o + 8) * NDS + n] = make_float2(r2, r3);
            *(__half2*)&g_efdh[(size_t)(b * 64 + o) * NDS + n]     = __floats2half2_rn(r0, r1);
            *(__half2*)&g_efdh[(size_t)(b * 64 + o + 8) * NDS + n] = __floats2half2_rn(r2, r3);
        }
    }
}

// ============================================================================
// K2: qkv (unchanged)
// ============================================================================
#define QKV_SMEM (4 * 64 * 72 * 2)

__global__ __launch_bounds__(128) void qkv_kernel(
    const float* __restrict__ xw1, const float* __restrict__ xb1,
    const float* __restrict__ qw,  const float* __restrict__ qb,
    const float* __restrict__ kw,  const float* __restrict__ kb,
    const float* __restrict__ vw,  const float* __restrict__ vb)
{
    extern __shared__ char smc[];
    unsigned smu = (unsigned)__cvta_generic_to_shared(smc);
    __half* W   = (__half*)smc;
    __half* Act = W + 64 * 72;
    __half* Tb  = Act + 64 * 72;
    __half* Tr  = Tb + 64 * 72;
    unsigned oW = smu, oAct = smu + 9216, oTb = smu + 18432;

    int t = threadIdx.x, lane = t & 31, w = t >> 5;
    int gid = lane >> 2, tig = lane & 3;
    int blk = blockIdx.x, b = blockIdx.y;
    int n0 = blk << 6;
    int o = (w << 4) + gid;

    for (int i = t; i < 512; i += 128) {
        int row = i >> 3, off = i & 7;
        *(uint4*)&Act[row * 72 + off * 8] =
            *(const uint4*)&g_xdsh[(size_t)(b * 64 + row) * NDS + n0 + off * 8];
    }
    for (int i = t; i < 4096; i += 128)
        W[(i >> 6) * 72 + (i & 63)] = __float2half_rn(xw1[i]);
    __syncthreads();

    float acc[8][4];
    #pragma unroll
    for (int nc = 0; nc < 8; nc++)
        #pragma unroll
        for (int q = 0; q < 4; q++) acc[nc][q] = 0.0f;
    gemm1p(acc, oW + (w * 16) * 144, 72, oAct, 4, lane);
    {
        float b0 = __ldg(&xb1[o]), b1 = __ldg(&xb1[o + 8]);
        #pragma unroll
        for (int nc = 0; nc < 8; nc++) {
            int px = nc * 8 + tig * 2;
            *(__half2*)&Tb[o * 72 + px] = __floats2half2_rn(
                fmaxf(acc[nc][0] + b0, 0.0f), fmaxf(acc[nc][1] + b0, 0.0f));
            *(__half2*)&Tb[(o + 8) * 72 + px] = __floats2half2_rn(
                fmaxf(acc[nc][2] + b1, 0.0f), fmaxf(acc[nc][3] + b1, 0.0f));
        }
    }
    __syncthreads();
    for (int i = t; i < 4096; i += 128)
        W[(i >> 6) * 72 + (i & 63)] = __float2half_rn(qw[i]);
    __syncthreads();

    #pragma unroll
    for (int nc = 0; nc < 8; nc++)
        #pragma unroll
        for (int q = 0; q < 4; q++) acc[nc][q] = 0.0f;
    gemm1p(acc, oW + (w * 16) * 144, 72, oTb, 4, lane);
    {
        float b0 = __ldg(&qb[o]), b1 = __ldg(&qb[o + 8]);
        #pragma unroll
        for (int nc = 0; nc < 8; nc++) {
            int px = nc * 8 + tig * 2;
            Tr[px * 72 + o]           = __float2half_rn(fmaxf(acc[nc][0] + b0, 0.0f));
            Tr[(px + 1) * 72 + o]     = __float2half_rn(fmaxf(acc[nc][1] + b0, 0.0f));
            Tr[px * 72 + o + 8]       = __float2half_rn(fmaxf(acc[nc][2] + b1, 0.0f));
            Tr[(px + 1) * 72 + o + 8] = __float2half_rn(fmaxf(acc[nc][3] + b1, 0.0f));
        }
    }
    __syncthreads();
    for (int i = t; i < 512; i += 128) {
        int row = i >> 3, off = i & 7;
        *(uint4*)&g_qh[((size_t)b * NDS + n0 + row) * 64 + off * 8] =
            *(uint4*)&Tr[row * 72 + off * 8];
    }
    for (int i = t; i < 4096; i += 128)
        W[(i >> 6) * 72 + (i & 63)] = __float2half_rn(vw[i]);
    __syncthreads();

    #pragma unroll
    for (int nc = 0; nc < 8; nc++)
        #pragma unroll
        for (int q = 0; q < 4; q++) acc[nc][q] = 0.0f;
    gemm1p(acc, oW + (w * 16) * 144, 72, oTb, 4, lane);
    {
        float b0 = __ldg(&vb[o]), b1 = __ldg(&vb[o + 8]);
        #pragma unroll
        for (int nc = 0; nc < 8; nc++) {
            int px = nc * 8 + tig * 2;
            Tr[px * 72 + o]           = __float2half_rn(fmaxf(acc[nc][0] + b0, 0.0f));
            Tr[(px + 1) * 72 + o]     = __float2half_rn(fmaxf(acc[nc][1] + b0, 0.0f));
            Tr[px * 72 + o + 8]       = __float2half_rn(fmaxf(acc[nc][2] + b1, 0.0f));
            Tr[(px + 1) * 72 + o + 8] = __float2half_rn(fmaxf(acc[nc][3] + b1, 0.0f));
        }
    }
    __syncthreads();
    for (int i = t; i < 512; i += 128) {
        int row = i >> 3, off = i & 7;
        *(uint4*)&g_vh[((size_t)b * NDS + n0 + row) * 64 + off * 8] =
            *(uint4*)&Tr[row * 72 + off * 8];
    }
    for (int i = t; i < 4096; i += 128)
        W[(i >> 6) * 72 + (i & 63)] = __float2half_rn(kw[i]);
    for (int i = t; i < 512; i += 128) {
        int row = i >> 3, off = i & 7;
        *(uint4*)&Act[row * 72 + off * 8] =
            *(const uint4*)&g_efdh[(size_t)(b * 64 + row) * NDS + n0 + off * 8];
    }
    __syncthreads();

    #pragma unroll
    for (int nc = 0; nc < 8; nc++)
        #pragma unroll
        for (int q = 0; q < 4; q++) acc[nc][q] = 0.0f;
    gemm1p(acc, oW + (w * 16) * 144, 72, oAct, 4, lane);
    {
        float b0 = __ldg(&kb[o]), b1 = __ldg(&kb[o + 8]);
        #pragma unroll
        for (int nc = 0; nc < 8; nc++) {
            int px = nc * 8 + tig * 2;
            Tr[px * 72 + o]           = __float2half_rn(fmaxf(acc[nc][0] + b0, 0.0f));
            Tr[(px + 1) * 72 + o]     = __float2half_rn(fmaxf(acc[nc][1] + b0, 0.0f));
            Tr[px * 72 + o + 8]       = __float2half_rn(fmaxf(acc[nc][2] + b1, 0.0f));
            Tr[(px + 1) * 72 + o + 8] = __float2half_rn(fmaxf(acc[nc][3] + b1, 0.0f));
        }
    }
    __syncthreads();
    for (int i = t; i < 512; i += 128) {
        int row = i >> 3, off = i & 7;
        *(uint4*)&g_kh[((size_t)b * NDS + n0 + row) * 64 + off * 8] =
            *(uint4*)&Tr[row * 72 + off * 8];
    }
}

// ============================================================================
// K3: flash attention — split-KV x2, 64-thr CTAs; PV/row-sum f16 accumulators.
// ============================================================================
#define SM_STRIDE 72
#define ATTN_SMEM ((64 * SM_STRIDE + 4 * 64 * SM_STRIDE) * 2)   // 46080

__global__ __launch_bounds__(64, 4) void attn_kernel()
{
    extern __shared__ __half smh[];
    __half* qs  = smh;
    __half* ks0 = smh + 64 * SM_STRIDE;
    __half* vs0 = ks0 + 2 * 64 * SM_STRIDE;

    int tid  = threadIdx.x;
    int lane = tid & 31, w = tid >> 5;
    int gid  = lane >> 2, tig = lane & 3;
    int b    = blockIdx.y;
    int m0   = blockIdx.x << 6;
    int split = blockIdx.z;
    int it0  = split << 5;

    const __half* qg = g_qh + (size_t)b * NDS * 64;
    const __half* kg = g_kh + (size_t)b * NDS * 64;
    const __half* vg = g_vh + (size_t)b * NDS * 64;

    unsigned qs_base = (unsigned)__cvta_generic_to_shared(qs);
    unsigned ks_base = (unsigned)__cvta_generic_to_shared(ks0);
    unsigned vs_base = (unsigned)__cvta_generic_to_shared(vs0);

    #pragma unroll
    for (int rep = 0; rep < 8; rep++) {
        int c = tid + rep * 64;
        int row = c >> 3, off = c & 7;
        cpasync16(ks_base + (row * SM_STRIDE + off * 8) * 2,
                  kg + (size_t)(it0 * 64 + row) * 64 + off * 8);
        cpasync16(vs_base + (row * SM_STRIDE + off * 8) * 2,
                  vg + (size_t)(it0 * 64 + row) * 64 + off * 8);
    }
    asm volatile("cp.async.commit_group;\n");

    asm volatile("griddepcontrol.launch_dependents;" ::: "memory");

    for (int c = tid; c < 512; c += 64) {
        int row = c >> 3, off = c & 7;
        *(uint4*)(qs + row * SM_STRIDE + off * 8) =
            *(const uint4*)(qg + (size_t)(m0 + row) * 64 + off * 8);
    }
    asm volatile("cp.async.wait_group 0;\n");
    __syncthreads();

    unsigned qa[2][4][4];
    #pragma unroll
    for (int s = 0; s < 2; s++) {
        int row = (w << 5) + (s << 4) + (lane & 15);
        #pragma unroll
        for (int kc = 0; kc < 4; kc++) {
            int dof = kc * 16 + (lane >> 4) * 8;
            ldm4(qa[s][kc], qs_base + (row * SM_STRIDE + dof) * 2);
        }
    }

    unsigned Ofh[2][8][2];       // f16x2 accumulators
    #pragma unroll
    for (int s = 0; s < 2; s++)
        #pragma unroll
        for (int dc = 0; dc < 8; dc++) {
            Ofh[s][dc][0] = 0u; Ofh[s][dc][1] = 0u;
        }
    float mrow[2][2], lrow[2][2];
    #pragma unroll
    for (int s = 0; s < 2; s++) {
        mrow[s][0] = -1e30f; mrow[s][1] = -1e30f;
        lrow[s][0] = 0.0f;   lrow[s][1] = 0.0f;
    }
    const unsigned ONES = 0x3C003C00u;

    for (int itr = 0; itr < 32; itr++) {
        int bf = itr & 1;
        unsigned ksb = ks_base + bf * 64 * SM_STRIDE * 2;
        unsigned vsb = vs_base + bf * 64 * SM_STRIDE * 2;

        if (itr + 1 < 32) {
            int n0n = (it0 + itr + 1) << 6;
            int nb  = (itr + 1) & 1;
            #pragma unroll
            for (int rep = 0; rep < 8; rep++) {
                int c = tid + rep * 64;
                int row = c >> 3, off = c & 7;
                cpasync16(ks_base + (nb * 64 * SM_STRIDE + row * SM_STRIDE + off * 8) * 2,
                          kg + (size_t)(n0n + row) * 64 + off * 8);
                cpasync16(vs_base + (nb * 64 * SM_STRIDE + row * SM_STRIDE + off * 8) * 2,
                          vg + (size_t)(n0n + row) * 64 + off * 8);
            }
            asm volatile("cp.async.commit_group;\n");
        }

        // S = Q @ K^T (f32 acc)
        float S[2][8][4];
        #pragma unroll
        for (int nc = 0; nc < 8; nc++) {
            unsigned kb[8];
            int krow = nc * 8 + (lane & 7);
            int kd   = (lane >> 3) * 8;
            ldm4(kb,     ksb + (krow * SM_STRIDE + kd) * 2);
            ldm4(kb + 4, ksb + (krow * SM_STRIDE + 32 + kd) * 2);
            #pragma unroll
            for (int s = 0; s < 2; s++) {
                #pragma unroll
                for (int q = 0; q < 4; q++) S[s][nc][q] = 0.0f;
                mma16816(S[s][nc], qa[s][0][0], qa[s][0][1], qa[s][0][2], qa[s][0][3], kb[0], kb[1]);
                mma16816(S[s][nc], qa[s][1][0], qa[s][1][1], qa[s][1][2], qa[s][1][3], kb[2], kb[3]);
                mma16816(S[s][nc], qa[s][2][0], qa[s][2][1], qa[s][2][2], qa[s][2][3], kb[4], kb[5]);
                mma16816(S[s][nc], qa[s][3][0], qa[s][3][1], qa[s][3][2], qa[s][3][3], kb[6], kb[7]);
            }
        }

        unsigned P[2][4][4];
        #pragma unroll
        for (int s = 0; s < 2; s++) {
            float tm0 = fmaxf(S[s][0][0], S[s][0][1]);
            float tm1 = fmaxf(S[s][0][2], S[s][0][3]);
            #pragma unroll
            for (int nc = 1; nc < 8; nc++) {
                tm0 = fmaxf(tm0, fmaxf(S[s][nc][0], S[s][nc][1]));
                tm1 = fmaxf(tm1, fmaxf(S[s][nc][2], S[s][nc][3]));
            }
            tm0 = fmaxf(tm0, __shfl_xor_sync(0xffffffffu, tm0, 1));
            tm0 = fmaxf(tm0, __shfl_xor_sync(0xffffffffu, tm0, 2));
            tm1 = fmaxf(tm1, __shfl_xor_sync(0xffffffffu, tm1, 1));
            tm1 = fmaxf(tm1, __shfl_xor_sync(0xffffffffu, tm1, 2));
            float nm0 = fmaxf(mrow[s][0], tm0), nm1 = fmaxf(mrow[s][1], tm1);
            float sc0 = exp2f((mrow[s][0] - nm0) * 1.44269504f);
            float sc1 = exp2f((mrow[s][1] - nm1) * 1.44269504f);
            mrow[s][0] = nm0; mrow[s][1] = nm1;
            float c0 = 1064866805.0f - nm0 * 12102203.16f;
            float c1 = 1064866805.0f - nm1 * 12102203.16f;

            #pragma unroll
            for (int jc = 0; jc < 4; jc++) {
                P[s][jc][0] = packh2(sexp(S[s][2*jc][0],   c0), sexp(S[s][2*jc][1],   c0));
                P[s][jc][1] = packh2(sexp(S[s][2*jc][2],   c1), sexp(S[s][2*jc][3],   c1));
                P[s][jc][2] = packh2(sexp(S[s][2*jc+1][0], c0), sexp(S[s][2*jc+1][1], c0));
                P[s][jc][3] = packh2(sexp(S[s][2*jc+1][2], c1), sexp(S[s][2*jc+1][3], c1));
            }

            unsigned lf[2] = {0u, 0u};
            #pragma unroll
            for (int jc = 0; jc < 4; jc++)
                mma16816h(lf, P[s][jc][0], P[s][jc][1], P[s][jc][2], P[s][jc][3], ONES, ONES);
            __half2 l0h = *(__half2*)&lf[0];
            __half2 l1h = *(__half2*)&lf[1];
            lrow[s][0] = lrow[s][0] * sc0 + __low2float(l0h);
            lrow[s][1] = lrow[s][1] * sc1 + __low2float(l1h);

            __half2 hs0 = __float2half2_rn(sc0);
            __half2 hs1 = __float2half2_rn(sc1);
            #pragma unroll
            for (int dc = 0; dc < 8; dc++) {
                __half2 a0 = *(__half2*)&Ofh[s][dc][0];
                __half2 a1 = *(__half2*)&Ofh[s][dc][1];
                a0 = __hmul2(a0, hs0);
                a1 = __hmul2(a1, hs1);
                Ofh[s][dc][0] = *(unsigned*)&a0;
                Ofh[s][dc][1] = *(unsigned*)&a1;
            }
        }

        // O += P @ V (f16 acc)
        #pragma unroll
        for (int jc = 0; jc < 4; jc++) {
            int vrow = jc * 16 + (lane & 15);
            int vcb  = (lane >> 4) * 8;
            #pragma unroll
            for (int dcp = 0; dcp < 4; dcp++) {
                unsigned vb[4];
                ldm4t(vb, vsb + (vrow * SM_STRIDE + dcp * 16 + vcb) * 2);
                #pragma unroll
                for (int s = 0; s < 2; s++) {
                    mma16816h(Ofh[s][2*dcp],     P[s][jc][0], P[s][jc][1], P[s][jc][2], P[s][jc][3], vb[0], vb[1]);
                    mma16816h(Ofh[s][2*dcp + 1], P[s][jc][0], P[s][jc][1], P[s][jc][2], P[s][jc][3], vb[2], vb[3]);
                }
            }
        }

        if (itr + 1 < 32) {
            asm volatile("cp.async.wait_group 0;\n");
            __syncthreads();
        }
    }

    float* Op = g_Op + (size_t)split * BATCH * CHN * NDS;
    #pragma unroll
    for (int s = 0; s < 2; s++) {
        int m = m0 + (w << 5) + (s << 4) + gid;
        #pragma unroll
        for (int dc = 0; dc < 8; dc++) {
            int d0 = dc * 8 + tig * 2;
            __half2 v0 = *(__half2*)&Ofh[s][dc][0];
            __half2 v1 = *(__half2*)&Ofh[s][dc][1];
            Op[(b * 64 + d0)     * NDS + m]     = __low2float(v0);
            Op[(b * 64 + d0 + 1) * NDS + m]     = __high2float(v0);
            Op[(b * 64 + d0)     * NDS + m + 8] = __low2float(v1);
            Op[(b * 64 + d0 + 1) * NDS + m + 8] = __high2float(v1);
        }
        if (tig == 0) {
            float* ml = g_ml + (size_t)((split * BATCH + b) * 2) * NDS;
            ml[m]           = mrow[s][0];
            ml[m + 8]       = mrow[s][1];
            ml[NDS + m]     = lrow[s][0];
            ml[NDS + m + 8] = lrow[s][1];
        }
    }
}

// ============================================================================
// K4: convout — 256 threads / 256-px tiles; fused combine epilogue.
// OS/ES stride 68 floats (16B-aligned rows; round-13 bug was stride 66).
// ============================================================================
#define CO_OFF_WH  0
#define CO_OFF_WL  25600
#define CO_OFF_STG 51200
#define CO_STG_BUF 16384
#define CO_OFF_ACT 83968
#define CO_ACT_BUF 8448
#define CONVOUT_SMEM (83968 + 2 * 8448)  // 100864
// epilogue overlay at CO_OFF_STG: OS[64][68] + ES[64][68] + SS0[64] + SS1[64]
//   = 2*64*68*4 + 512 = 35328 <= 49664 available ✓

__device__ __forceinline__ void co_issue_stage(
    const float* __restrict__ x1, const float* __restrict__ x2,
    int b, int p0, int t, unsigned dstbase, int ks)
{
    #pragma unroll
    for (int rep = 0; rep < 4; rep++) {
        int i = t + rep * 256;
        int row = i >> 6, off = i & 63;
        int c = ks * 16 + row;
        const float* src = (c < 128) ? x1 + (size_t)(b * 128 + c) * HW
                                     : x2 + (size_t)(b * 64 + c - 128) * HW;
        cpasync16(dstbase + row * 1024 + off * 16, src + p0 + off * 4);
    }
    asm volatile("cp.async.commit_group;\n");
}

__device__ __forceinline__ void co_convert(const float* stg, __half* AH, int t)
{
    #pragma unroll
    for (int ch = 0; ch < 4; ch++) {
        int i = ch * 1024 + t * 4;
        int row = i >> 8, col = i & 255;
        float4 v = *(const float4*)(stg + i);
        __half2 h0 = __floats2half2_rn(v.x, v.y);
        __half2 h1 = __floats2half2_rn(v.z, v.w);
        uint2 u;
        u.x = *(unsigned*)&h0;
        u.y = *(unsigned*)&h1;
        *(uint2*)&AH[row * 264 + col] = u;
    }
}

__global__ __launch_bounds__(256) void convout_kernel(
    const float* __restrict__ x1, const float* __restrict__ x2,
    const float* __restrict__ bias,
    const float* __restrict__ gamma, float* __restrict__ out)
{
    extern __shared__ char smc[];
    unsigned smu = (unsigned)__cvta_generic_to_shared(smc);

    int t = threadIdx.x;
    int lane = t & 31, wp = t >> 5;
    int ln15 = lane & 15, hb8 = (lane >> 4) * 8;
    int y = blockIdx.x, b = blockIdx.y;
    int p0 = y << 8;
    int ndbase = (y >> 2) << 6;

    #pragma unroll
    for (int rep = 0; rep < 7; rep++) {
        int i = t + rep * 256;
        if (i < 1600) {
            cpasync16(smu + CO_OFF_WH + i * 16, (const char*)g_wh + i * 16);
            cpasync16(smu + CO_OFF_WL + i * 16, (const char*)g_wl + i * 16);
        }
    }
    co_issue_stage(x1, x2, b, p0, t, smu + CO_OFF_STG, 0);
    co_issue_stage(x1, x2, b, p0, t, smu + CO_OFF_STG + CO_STG_BUF, 1);

    asm volatile("cp.async.wait_group 1;\n");
    __syncthreads();
    co_convert((const float*)(smc + CO_OFF_STG), (__half*)(smc + CO_OFF_ACT), t);

    float acc[4][4][4];
    #pragma unroll
    for (int mt = 0; mt < 4; mt++)
        #pragma unroll
        for (int nb = 0; nb < 4; nb++)
            #pragma unroll
            for (int q = 0; q < 4; q++) acc[mt][nb][q] = 0.0f;

    unsigned whB = smu + CO_OFF_WH + (ln15 * 200 + hb8) * 2;
    unsigned wlB = smu + CO_OFF_WL + (ln15 * 200 + hb8) * 2;

    #pragma unroll 1
    for (int ks = 0; ks < 12; ks++) {
        __syncthreads();
        if (ks + 2 < 12)
            co_issue_stage(x1, x2, b, p0, t,
                           smu + CO_OFF_STG + (ks & 1) * CO_STG_BUF, ks + 2);

        unsigned actH = smu + CO_OFF_ACT + (ks & 1) * CO_ACT_BUF +
                        (ln15 * 264 + wp * 32 + hb8) * 2;
        unsigned Bh[8], A[4][4];
        ldm4t(Bh,     actH);
        ldm4t(Bh + 4, actH + 32);
        #pragma unroll
        for (int mt = 0; mt < 4; mt++)
            ldm4(A[mt], whB + mt * 6400 + ks * 32);
        #pragma unroll
        for (int mt = 0; mt < 4; mt++) {
            mma16816(acc[mt][0], A[mt][0], A[mt][1], A[mt][2], A[mt][3], Bh[0], Bh[1]);
            mma16816(acc[mt][1], A[mt][0], A[mt][1], A[mt][2], A[mt][3], Bh[2], Bh[3]);
            mma16816(acc[mt][2], A[mt][0], A[mt][1], A[mt][2], A[mt][3], Bh[4], Bh[5]);
            mma16816(acc[mt][3], A[mt][0], A[mt][1], A[mt][2], A[mt][3], Bh[6], Bh[7]);
        }
        #pragma unroll
        for (int mt = 0; mt < 4; mt++)
            ldm4(A[mt], wlB + mt * 6400 + ks * 32);
        #pragma unroll
        for (int mt = 0; mt < 4; mt++) {
            mma16816(acc[mt][0], A[mt][0], A[mt][1], A[mt][2], A[mt][3], Bh[0], Bh[1]);
            mma16816(acc[mt][1], A[mt][0], A[mt][1], A[mt][2], A[mt][3], Bh[2], Bh[3]);
            mma16816(acc[mt][2], A[mt][0], A[mt][1], A[mt][2], A[mt][3], Bh[4], Bh[5]);
            mma16816(acc[mt][3], A[mt][0], A[mt][1], A[mt][2], A[mt][3], Bh[6], Bh[7]);
        }

        if (ks + 1 < 12) {
            if (ks + 2 < 12) { asm volatile("cp.async.wait_group 1;\n"); }
            else             { asm volatile("cp.async.wait_group 0;\n"); }
            co_convert((const float*)(smc + CO_OFF_STG + ((ks + 1) & 1) * CO_STG_BUF),
                       (__half*)(smc + CO_OFF_ACT + ((ks + 1) & 1) * CO_ACT_BUF), t);
        }
    }

    // wait for attn, then fused split-KV combine + epilogue
    asm volatile("griddepcontrol.wait;" ::: "memory");
    __syncthreads();

    float* OS  = (float*)(smc + CO_OFF_STG);       // [64][68] combined O
    float* ES  = OS + 64 * 68;                     // [64][68] ef
    float* SS0 = ES + 64 * 68;                     // [64]
    float* SS1 = SS0 + 64;

    if (t < 64) {
        int nd = ndbase + t;
        float m0 = g_ml[(size_t)((0 * BATCH + b) * 2) * NDS + nd];
        float l0 = g_ml[(size_t)((0 * BATCH + b) * 2) * NDS + NDS + nd];
        float m1 = g_ml[(size_t)((1 * BATCH + b) * 2) * NDS + nd];
        float l1 = g_ml[(size_t)((1 * BATCH + b) * 2) * NDS + NDS + nd];
        float M  = fmaxf(m0, m1);
        float s0 = exp2f((m0 - M) * 1.44269504f);
        float s1 = exp2f((m1 - M) * 1.44269504f);
        float inv = 1.0f / (l0 * s0 + l1 * s1);
        SS0[t] = s0 * inv;
        SS1[t] = s1 * inv;
    }
    __syncthreads();

    {
        int o = t >> 2, c0 = (t & 3) << 4;
        const float* po0 = g_Op + (size_t)(b * 64 + o) * NDS + ndbase + c0;
        const float* po1 = g_Op + (size_t)(BATCH * CHN + b * 64 + o) * NDS + ndbase + c0;
        const float* pe  = g_efd + (size_t)(b * 64 + o) * NDS + ndbase + c0;
        #pragma unroll
        for (int j = 0; j < 4; j++) {
            float4 a0 = *(const float4*)(po0 + 4 * j);
            float4 a1 = *(const float4*)(po1 + 4 * j);
            int cc = c0 + 4 * j;
            float4 r;
            r.x = a0.x * SS0[cc]     + a1.x * SS1[cc];
            r.y = a0.y * SS0[cc + 1] + a1.y * SS1[cc + 1];
            r.z = a0.z * SS0[cc + 2] + a1.z * SS1[cc + 2];
            r.w = a0.w * SS0[cc + 3] + a1.w * SS1[cc + 3];
            *(float4*)&OS[o * 68 + cc] = r;
            *(float4*)&ES[o * 68 + cc] = *(const float4*)(pe + 4 * j);
        }
    }
    __syncthreads();

    float tg = THITA_F * __ldg(gamma);
    int g = lane >> 2, tig = lane & 3;
    #pragma unroll
    for (int mt = 0; mt < 4; mt++) {
        int o = mt * 16 + g;
        float bb0 = __ldg(&bias[o]), bb1 = __ldg(&bias[o + 8]);
        #pragma unroll
        for (int nb = 0; nb < 4; nb++) {
            int px = wp * 32 + nb * 8 + tig * 2;
            int ndc = px >> 2;
            float a0 = tg * OS[o * 68 + ndc];
            float a1 = tg * OS[(o + 8) * 68 + ndc];
            float2 r0 = make_float2(fmaxf(acc[mt][nb][0] + bb0, 0.0f) + a0,
                                    fmaxf(acc[mt][nb][1] + bb0, 0.0f) + a0);
            float2 r1 = make_float2(fmaxf(acc[mt][nb][2] + bb1, 0.0f) + a1,
                                    fmaxf(acc[mt][nb][3] + bb1, 0.0f) + a1);
            *(float2*)(out + (size_t)(b * 64 + o)     * HW + p0 + px) = r0;
            *(float2*)(out + (size_t)(b * 64 + o + 8) * HW + p0 + px) = r1;
        }
    }

    int xq = t & 63;
    #pragma unroll
    for (int rep = 0; rep < 16; rep++) {
        int o = rep * 4 + (t >> 6);
        float v = ES[o * 68 + xq];
        *(float4*)(out + OUT2OFF + (size_t)(b * 64 + o) * HW + p0 + (xq << 2)) =
            make_float4(v, v, v, v);
    }
}

// ============================================================================
extern "C" void kernel_launch(void* const* d_in, const int* in_sizes, int n_in,
                              void* d_out, int out_size)
{
    const float* x1    = (const float*)d_in[0];
    const float* x2    = (const float*)d_in[1];
    const float* ev    = (const float*)d_in[2];
    const float* xw0   = (const float*)d_in[3];
    const float* xb0   = (const float*)d_in[4];
    const float* xw1   = (const float*)d_in[5];
    const float* xb1   = (const float*)d_in[6];
    const float* ew0   = (const float*)d_in[7];
    const float* eb0   = (const float*)d_in[8];
    const float* ew1   = (const float*)d_in[9];
    const float* eb1   = (const float*)d_in[10];
    const float* qw    = (const float*)d_in[11];
    const float* qb    = (const float*)d_in[12];
    const float* kw    = (const float*)d_in[13];
    const float* kb    = (const float*)d_in[14];
    const float* vw    = (const float*)d_in[15];
    const float* vb    = (const float*)d_in[16];
    const float* gamma = (const float*)d_in[17];
    float* out = (float*)d_out;

    cudaFuncSetAttribute(prep_kernel,
                         cudaFuncAttributeMaxDynamicSharedMemorySize, PREP_SMEM);
    cudaFuncSetAttribute(qkv_kernel,
                         cudaFuncAttributeMaxDynamicSharedMemorySize, QKV_SMEM);
    cudaFuncSetAttribute(attn_kernel,
                         cudaFuncAttributeMaxDynamicSharedMemorySize, ATTN_SMEM);
    cudaFuncSetAttribute(convout_kernel,
                         cudaFuncAttributeMaxDynamicSharedMemorySize, CONVOUT_SMEM);

    wconv_kernel<<<48, 256>>>(xw0);
    prep_kernel<<<dim3(NDS / 64, BATCH, 2), 128, PREP_SMEM>>>(
        x1, x2, ev, xw0, xb0, ew0, eb0, ew1, eb1);
    qkv_kernel<<<dim3(NDS / 64, BATCH), 128, QKV_SMEM>>>(
        xw1, xb1, qw, qb, kw, kb, vw, vb);
    attn_kernel<<<dim3(NDS / 64, BATCH, 2), 64, ATTN_SMEM>>>();

    {
        cudaLaunchConfig_t cfg = {};
        cfg.gridDim = dim3(256, BATCH, 1);
        cfg.blockDim = dim3(256, 1, 1);
        cfg.dynamicSmemBytes = CONVOUT_SMEM;
        cfg.stream = 0;
        cudaLaunchAttribute attrs[1];
        attrs[0].id = cudaLaunchAttributeProgrammaticStreamSerialization;
        attrs[0].val.programmaticStreamSerializationAllowed = 1;
        cfg.attrs = attrs;
        cfg.numAttrs = 1;
        cudaLaunchKernelEx(&cfg, convout_kernel, x1, x2, xb0, gamma, out);
    }
}

// round 15
// speedup vs baseline: 1.0826x; 1.0826x over previous
#include <cuda_runtime.h>
#include <cuda_fp16.h>
#include <math.h>

#define BATCH 4
#define CHN 64
#define HW 65536        // 256*256
#define NDS 4096        // 64*64 downsampled pixels
#define THITA_F 1.0e-4f
#define OUT2OFF (BATCH * CHN * HW)

// ---------------- scratch (device globals) ----------------------------------
__device__ __half g_xdsh[BATCH * CHN * NDS];    // down4(x) f16 [b][c][n]
__device__ float  g_efd [BATCH * CHN * NDS];    // ef ds fp32 [b][c][n]
__device__ __half g_efdh[BATCH * CHN * NDS];    // ef ds f16
__device__ __half g_qh[BATCH * NDS * CHN];      // [b][n][d] f16
__device__ __half g_kh[BATCH * NDS * CHN];
__device__ __half g_vh[BATCH * NDS * CHN];
__device__ float  g_Op[2 * BATCH * CHN * NDS];  // split-KV partial O (unnormalized)
__device__ float  g_ml[2 * BATCH * 2 * NDS];    // split-KV per-row m and l
__device__ __half g_wh[64 * 200];               // conv0 weights f16 hi
__device__ __half g_wl[64 * 200];               // conv0 weights f16 lo

// ============================================================================
// mma / ldmatrix helpers
// ============================================================================
__device__ __forceinline__ void mma16816(float* d,
    unsigned a0, unsigned a1, unsigned a2, unsigned a3,
    unsigned b0, unsigned b1)
{
    asm volatile(
        "mma.sync.aligned.m16n8k16.row.col.f32.f16.f16.f32 "
        "{%0,%1,%2,%3}, {%4,%5,%6,%7}, {%8,%9}, {%0,%1,%2,%3};\n"
        : "+f"(d[0]), "+f"(d[1]), "+f"(d[2]), "+f"(d[3])
        : "r"(a0), "r"(a1), "r"(a2), "r"(a3), "r"(b0), "r"(b1));
}
__device__ __forceinline__ void mma16816h(unsigned* d,
    unsigned a0, unsigned a1, unsigned a2, unsigned a3,
    unsigned b0, unsigned b1)
{
    asm volatile(
        "mma.sync.aligned.m16n8k16.row.col.f16.f16.f16.f16 "
        "{%0,%1}, {%2,%3,%4,%5}, {%6,%7}, {%0,%1};\n"
        : "+r"(d[0]), "+r"(d[1])
        : "r"(a0), "r"(a1), "r"(a2), "r"(a3), "r"(b0), "r"(b1));
}
__device__ __forceinline__ void ldm4(unsigned* r, unsigned a) {
    asm volatile("ldmatrix.sync.aligned.m8n8.x4.shared.b16 {%0,%1,%2,%3}, [%4];\n"
        : "=r"(r[0]), "=r"(r[1]), "=r"(r[2]), "=r"(r[3]) : "r"(a));
}
__device__ __forceinline__ void ldm4t(unsigned* r, unsigned a) {
    asm volatile("ldmatrix.sync.aligned.m8n8.x4.trans.shared.b16 {%0,%1,%2,%3}, [%4];\n"
        : "=r"(r[0]), "=r"(r[1]), "=r"(r[2]), "=r"(r[3]) : "r"(a));
}
__device__ __forceinline__ void cpasync16(unsigned dst, const void* src) {
    asm volatile("cp.async.cg.shared.global [%0], [%1], 16;\n"
        :: "r"(dst), "l"(src));
}
__device__ __forceinline__ unsigned hpack(__half a, __half b) {
    __half2 h = __halves2half2(a, b);
    return *(unsigned*)&h;
}
__device__ __forceinline__ unsigned packh2(float a, float b) {
    __half2 h = __floats2half2_rn(a, b);
    return *(unsigned*)&h;
}
__device__ __forceinline__ float sexp(float s, float c) {
    float t = fmaf(s, 12102203.16f, c);
    t = fmaxf(t, 0.0f);
    return __int_as_float(__float2int_rn(t));
}

// single-pass f16 GEMM
__device__ __forceinline__ void gemm1p(float acc[8][4], unsigned wb, int wstride,
                                       unsigned ab, int nks, int lane)
{
    int ln15 = lane & 15, hb8 = (lane >> 4) * 8;
    unsigned wl = wb + (ln15 * wstride + hb8) * 2;
    #pragma unroll
    for (int ks = 0; ks < nks; ks++) {
        unsigned al = ab + ((ks * 16 + ln15) * 72 + hb8) * 2;
        unsigned B[16], A[4];
        ldm4t(B,      al);
        ldm4t(B + 4,  al + 32);
        ldm4t(B + 8,  al + 64);
        ldm4t(B + 12, al + 96);
        ldm4(A, wl + ks * 32);
        #pragma unroll
        for (int nc = 0; nc < 8; nc++) {
            int ib = (nc >> 1) * 4 + (nc & 1) * 2;
            mma16816(acc[nc], A[0], A[1], A[2], A[3], B[ib], B[ib + 1]);
        }
    }
}

// 3-pass hi/lo GEMM (K=64)
__device__ __forceinline__ void gemm3p(float acc[8][4],
    unsigned wh, unsigned wlo, unsigned ah, unsigned alo, int lane)
{
    int ln15 = lane & 15, hb8 = (lane >> 4) * 8;
    unsigned wbh = wh  + (ln15 * 72 + hb8) * 2;
    unsigned wbl = wlo + (ln15 * 72 + hb8) * 2;
    #pragma unroll
    for (int ks = 0; ks < 4; ks++) {
        unsigned abh = ah  + ((ks * 16 + ln15) * 72 + hb8) * 2;
        unsigned abl = alo + ((ks * 16 + ln15) * 72 + hb8) * 2;
        unsigned Bh[16], Bl[16], Wf[4], Lf[4];
        ldm4t(Bh,      abh);
        ldm4t(Bh + 4,  abh + 32);
        ldm4t(Bh + 8,  abh + 64);
        ldm4t(Bh + 12, abh + 96);
        ldm4t(Bl,      abl);
        ldm4t(Bl + 4,  abl + 32);
        ldm4t(Bl + 8,  abl + 64);
        ldm4t(Bl + 12, abl + 96);
        ldm4(Wf, wbh + ks * 32);
        ldm4(Lf, wbl + ks * 32);
        #pragma unroll
        for (int nc = 0; nc < 8; nc++) {
            int ib = (nc >> 1) * 4 + (nc & 1) * 2;
            mma16816(acc[nc], Wf[0], Wf[1], Wf[2], Wf[3], Bh[ib], Bh[ib + 1]);
            mma16816(acc[nc], Wf[0], Wf[1], Wf[2], Wf[3], Bl[ib], Bl[ib + 1]);
            mma16816(acc[nc], Lf[0], Lf[1], Lf[2], Lf[3], Bh[ib], Bh[ib + 1]);
        }
    }
}

// ============================================================================
// K0: wconv
// ============================================================================
__global__ void wconv_kernel(const float* __restrict__ w)
{
    int i = blockIdx.x * 256 + threadIdx.x;
    if (i < 12288) {
        int o = i / 192, c = i - o * 192;
        float v = w[i];
        __half h = __float2half_rn(v);
        g_wh[o * 200 + c] = h;
        g_wl[o * 200 + c] = __float2half_rn(v - __half2float(h));
    }
}

// ============================================================================
// K1: prep — z=0: conv0_ds (f16 1-pass) -> g_xdsh; z=1: ef chain (3-pass)
// ============================================================================
#define PREP_SMEM (64 * 200 * 2 + 192 * 72 * 2)

__global__ __launch_bounds__(128) void prep_kernel(
    const float* __restrict__ x1, const float* __restrict__ x2,
    const float* __restrict__ ev,
    const float* __restrict__ xw0, const float* __restrict__ xb0,
    const float* __restrict__ ew0, const float* __restrict__ eb0,
    const float* __restrict__ ew1, const float* __restrict__ eb1)
{
    extern __shared__ char smc[];
    unsigned smu = (unsigned)__cvta_generic_to_shared(smc);
    int t = threadIdx.x, lane = t & 31, w = t >> 5;
    int gid = lane >> 2, tig = lane & 3;
    int blk = blockIdx.x, b = blockIdx.y;
    int n0 = blk << 6;

    float acc[8][4];
    #pragma unroll
    for (int nc = 0; nc < 8; nc++)
        #pragma unroll
        for (int q = 0; q < 4; q++) acc[nc][q] = 0.0f;

    if (blockIdx.z == 0) {
        __half* W  = (__half*)smc;
        __half* Ac = (__half*)(smc + 64 * 200 * 2);
        for (int i = t; i < 12288; i += 128) {
            int o = i / 192, c = i - o * 192;
            W[o * 200 + c] = __float2half_rn(xw0[i]);
        }
        for (int i = t; i < 12288; i += 128) {
            int c = i >> 6, x = i & 63;
            const float* s = (c < 128) ? x1 + (size_t)(b * 128 + c) * HW
                                       : x2 + (size_t)(b * 64 + c - 128) * HW;
            Ac[c * 72 + x] = __float2half_rn(s[(blk << 10) + (x << 2)]);
        }
        __syncthreads();

        gemm1p(acc, smu + (w * 16) * 200 * 2, 200,
               smu + 64 * 200 * 2, 12, lane);

        int o = (w << 4) + gid;
        float b0 = __ldg(&xb0[o]), b1 = __ldg(&xb0[o + 8]);
        #pragma unroll
        for (int nc = 0; nc < 8; nc++) {
            int n = n0 + nc * 8 + tig * 2;
            *(__half2*)&g_xdsh[(size_t)(b * 64 + o) * NDS + n] =
                __floats2half2_rn(fmaxf(acc[nc][0] + b0, 0.0f),
                                  fmaxf(acc[nc][1] + b0, 0.0f));
            *(__half2*)&g_xdsh[(size_t)(b * 64 + o + 8) * NDS + n] =
                __floats2half2_rn(fmaxf(acc[nc][2] + b1, 0.0f),
                                  fmaxf(acc[nc][3] + b1, 0.0f));
        }
    } else {
        __half* Wh = (__half*)smc;
        __half* Wl = Wh + 64 * 72;
        __half* Ah = Wl + 64 * 72;
        __half* Al = Ah + 64 * 72;
        unsigned oWh = smu, oWl = smu + 9216, oAh = smu + 18432, oAl = smu + 27648;

        for (int i = t; i < 4096; i += 128) {
            float v = ew0[i];
            __half h = __float2half_rn(v);
            int o = i >> 6, c = i & 63;
            Wh[o * 72 + c] = h;
            Wl[o * 72 + c] = __float2half_rn(v - __half2float(h));
        }
        for (int i = t; i < 4096; i += 128) {
            int c = i >> 6, x = i & 63;
            float v = ev[(size_t)(b * 64 + c) * HW + (blk << 10) + (x << 2)];
            __half h = __float2half_rn(v);
            Ah[c * 72 + x] = h;
            Al[c * 72 + x] = __float2half_rn(v - __half2float(h));
        }
        __syncthreads();

        gemm3p(acc, oWh + (w * 16) * 144, oWl + (w * 16) * 144, oAh, oAl, lane);
        __syncthreads();

        {
            int o = (w << 4) + gid;
            float b0 = __ldg(&eb0[o]), b1 = __ldg(&eb0[o + 8]);
            #pragma unroll
            for (int nc = 0; nc < 8; nc++) {
                int px = nc * 8 + tig * 2;
                float t0 = fmaxf(acc[nc][0] + b0, 0.0f);
                float t1 = fmaxf(acc[nc][1] + b0, 0.0f);
                float t2 = fmaxf(acc[nc][2] + b1, 0.0f);
                float t3 = fmaxf(acc[nc][3] + b1, 0.0f);
                __half h0 = __float2half_rn(t0), h1 = __float2half_rn(t1);
                __half h2 = __float2half_rn(t2), h3 = __float2half_rn(t3);
                *(__half2*)&Ah[o * 72 + px] = __halves2half2(h0, h1);
                *(__half2*)&Al[o * 72 + px] = __floats2half2_rn(
                    t0 - __half2float(h0), t1 - __half2float(h1));
                *(__half2*)&Ah[(o + 8) * 72 + px] = __halves2half2(h2, h3);
                *(__half2*)&Al[(o + 8) * 72 + px] = __floats2half2_rn(
                    t2 - __half2float(h2), t3 - __half2float(h3));
            }
        }
        for (int i = t; i < 4096; i += 128) {
            float v = ew1[i];
            __half h = __float2half_rn(v);
            int o = i >> 6, c = i & 63;
            Wh[o * 72 + c] = h;
            Wl[o * 72 + c] = __float2half_rn(v - __half2float(h));
        }
        __syncthreads();

        #pragma unroll
        for (int nc = 0; nc < 8; nc++)
            #pragma unroll
            for (int q = 0; q < 4; q++) acc[nc][q] = 0.0f;
        gemm3p(acc, oWh + (w * 16) * 144, oWl + (w * 16) * 144, oAh, oAl, lane);

        int o = (w << 4) + gid;
        float b0 = __ldg(&eb1[o]), b1 = __ldg(&eb1[o + 8]);
        #pragma unroll
        for (int nc = 0; nc < 8; nc++) {
            int n = n0 + nc * 8 + tig * 2;
            float r0 = fmaxf(acc[nc][0] + b0, 0.0f);
            float r1 = fmaxf(acc[nc][1] + b0, 0.0f);
            float r2 = fmaxf(acc[nc][2] + b1, 0.0f);
            float r3 = fmaxf(acc[nc][3] + b1, 0.0f);
            *(float2*)&g_efd[(size_t)(b * 64 + o) * NDS + n]     = make_float2(r0, r1);
            *(float2*)&g_efd[(size_t)(b * 64 + o + 8) * NDS + n] = make_float2(r2, r3);
            *(__half2*)&g_efdh[(size_t)(b * 64 + o) * NDS + n]     = __floats2half2_rn(r0, r1);
            *(__half2*)&g_efdh[(size_t)(b * 64 + o + 8) * NDS + n] = __floats2half2_rn(r2, r3);
        }
    }
}

// ============================================================================
// K2: qkv — all f16 1-pass mma (unchanged)
// ============================================================================
#define QKV_SMEM (4 * 64 * 72 * 2)

__global__ __launch_bounds__(128) void qkv_kernel(
    const float* __restrict__ xw1, const float* __restrict__ xb1,
    const float* __restrict__ qw,  const float* __restrict__ qb,
    const float* __restrict__ kw,  const float* __restrict__ kb,
    const float* __restrict__ vw,  const float* __restrict__ vb)
{
    extern __shared__ char smc[];
    unsigned smu = (unsigned)__cvta_generic_to_shared(smc);
    __half* W   = (__half*)smc;
    __half* Act = W + 64 * 72;
    __half* Tb  = Act + 64 * 72;
    __half* Tr  = Tb + 64 * 72;
    unsigned oW = smu, oAct = smu + 9216, oTb = smu + 18432;

    int t = threadIdx.x, lane = t & 31, w = t >> 5;
    int gid = lane >> 2, tig = lane & 3;
    int blk = blockIdx.x, b = blockIdx.y;
    int n0 = blk << 6;
    int o = (w << 4) + gid;

    for (int i = t; i < 512; i += 128) {
        int row = i >> 3, off = i & 7;
        *(uint4*)&Act[row * 72 + off * 8] =
            *(const uint4*)&g_xdsh[(size_t)(b * 64 + row) * NDS + n0 + off * 8];
    }
    for (int i = t; i < 4096; i += 128)
        W[(i >> 6) * 72 + (i & 63)] = __float2half_rn(xw1[i]);
    __syncthreads();

    float acc[8][4];
    #pragma unroll
    for (int nc = 0; nc < 8; nc++)
        #pragma unroll
        for (int q = 0; q < 4; q++) acc[nc][q] = 0.0f;
    gemm1p(acc, oW + (w * 16) * 144, 72, oAct, 4, lane);
    {
        float b0 = __ldg(&xb1[o]), b1 = __ldg(&xb1[o + 8]);
        #pragma unroll
        for (int nc = 0; nc < 8; nc++) {
            int px = nc * 8 + tig * 2;
            *(__half2*)&Tb[o * 72 + px] = __floats2half2_rn(
                fmaxf(acc[nc][0] + b0, 0.0f), fmaxf(acc[nc][1] + b0, 0.0f));
            *(__half2*)&Tb[(o + 8) * 72 + px] = __floats2half2_rn(
                fmaxf(acc[nc][2] + b1, 0.0f), fmaxf(acc[nc][3] + b1, 0.0f));
        }
    }
    __syncthreads();
    for (int i = t; i < 4096; i += 128)
        W[(i >> 6) * 72 + (i & 63)] = __float2half_rn(qw[i]);
    __syncthreads();

    #pragma unroll
    for (int nc = 0; nc < 8; nc++)
        #pragma unroll
        for (int q = 0; q < 4; q++) acc[nc][q] = 0.0f;
    gemm1p(acc, oW + (w * 16) * 144, 72, oTb, 4, lane);
    {
        float b0 = __ldg(&qb[o]), b1 = __ldg(&qb[o + 8]);
        #pragma unroll
        for (int nc = 0; nc < 8; nc++) {
            int px = nc * 8 + tig * 2;
            Tr[px * 72 + o]           = __float2half_rn(fmaxf(acc[nc][0] + b0, 0.0f));
            Tr[(px + 1) * 72 + o]     = __float2half_rn(fmaxf(acc[nc][1] + b0, 0.0f));
            Tr[px * 72 + o + 8]       = __float2half_rn(fmaxf(acc[nc][2] + b1, 0.0f));
            Tr[(px + 1) * 72 + o + 8] = __float2half_rn(fmaxf(acc[nc][3] + b1, 0.0f));
        }
    }
    __syncthreads();
    for (int i = t; i < 512; i += 128) {
        int row = i >> 3, off = i & 7;
        *(uint4*)&g_qh[((size_t)b * NDS + n0 + row) * 64 + off * 8] =
            *(uint4*)&Tr[row * 72 + off * 8];
    }
    for (int i = t; i < 4096; i += 128)
        W[(i >> 6) * 72 + (i & 63)] = __float2half_rn(vw[i]);
    __syncthreads();

    #pragma unroll
    for (int nc = 0; nc < 8; nc++)
        #pragma unroll
        for (int q = 0; q < 4; q++) acc[nc][q] = 0.0f;
    gemm1p(acc, oW + (w * 16) * 144, 72, oTb, 4, lane);
    {
        float b0 = __ldg(&vb[o]), b1 = __ldg(&vb[o + 8]);
        #pragma unroll
        for (int nc = 0; nc < 8; nc++) {
            int px = nc * 8 + tig * 2;
            Tr[px * 72 + o]           = __float2half_rn(fmaxf(acc[nc][0] + b0, 0.0f));
            Tr[(px + 1) * 72 + o]     = __float2half_rn(fmaxf(acc[nc][1] + b0, 0.0f));
            Tr[px * 72 + o + 8]       = __float2half_rn(fmaxf(acc[nc][2] + b1, 0.0f));
            Tr[(px + 1) * 72 + o + 8] = __float2half_rn(fmaxf(acc[nc][3] + b1, 0.0f));
        }
    }
    __syncthreads();
    for (int i = t; i < 512; i += 128) {
        int row = i >> 3, off = i & 7;
        *(uint4*)&g_vh[((size_t)b * NDS + n0 + row) * 64 + off * 8] =
            *(uint4*)&Tr[row * 72 + off * 8];
    }
    for (int i = t; i < 4096; i += 128)
        W[(i >> 6) * 72 + (i & 63)] = __float2half_rn(kw[i]);
    for (int i = t; i < 512; i += 128) {
        int row = i >> 3, off = i & 7;
        *(uint4*)&Act[row * 72 + off * 8] =
            *(const uint4*)&g_efdh[(size_t)(b * 64 + row) * NDS + n0 + off * 8];
    }
    __syncthreads();

    #pragma unroll
    for (int nc = 0; nc < 8; nc++)
        #pragma unroll
        for (int q = 0; q < 4; q++) acc[nc][q] = 0.0f;
    gemm1p(acc, oW + (w * 16) * 144, 72, oAct, 4, lane);
    {
        float b0 = __ldg(&kb[o]), b1 = __ldg(&kb[o + 8]);
        #pragma unroll
        for (int nc = 0; nc < 8; nc++) {
            int px = nc * 8 + tig * 2;
            Tr[px * 72 + o]           = __float2half_rn(fmaxf(acc[nc][0] + b0, 0.0f));
            Tr[(px + 1) * 72 + o]     = __float2half_rn(fmaxf(acc[nc][1] + b0, 0.0f));
            Tr[px * 72 + o + 8]       = __float2half_rn(fmaxf(acc[nc][2] + b1, 0.0f));
            Tr[(px + 1) * 72 + o + 8] = __float2half_rn(fmaxf(acc[nc][3] + b1, 0.0f));
        }
    }
    __syncthreads();
    for (int i = t; i < 512; i += 128) {
        int row = i >> 3, off = i & 7;
        *(uint4*)&g_kh[((size_t)b * NDS + n0 + row) * 64 + off * 8] =
            *(uint4*)&Tr[row * 72 + off * 8];
    }
}

// ============================================================================
// K3: flash attention — split-KV x2, 64-thr CTAs, PV/row-sum f16 accumulators
// (round-14 version: 66.1us standalone, regs 213, 4 CTAs/SM).
// ============================================================================
#define SM_STRIDE 72
#define ATTN_SMEM ((64 * SM_STRIDE + 4 * 64 * SM_STRIDE) * 2)   // 46080

__global__ __launch_bounds__(64, 4) void attn_kernel()
{
    extern __shared__ __half smh[];
    __half* qs  = smh;
    __half* ks0 = smh + 64 * SM_STRIDE;
    __half* vs0 = ks0 + 2 * 64 * SM_STRIDE;

    int tid  = threadIdx.x;
    int lane = tid & 31, w = tid >> 5;
    int gid  = lane >> 2, tig = lane & 3;
    int b    = blockIdx.y;
    int m0   = blockIdx.x << 6;
    int split = blockIdx.z;
    int it0  = split << 5;

    const __half* qg = g_qh + (size_t)b * NDS * 64;
    const __half* kg = g_kh + (size_t)b * NDS * 64;
    const __half* vg = g_vh + (size_t)b * NDS * 64;

    unsigned qs_base = (unsigned)__cvta_generic_to_shared(qs);
    unsigned ks_base = (unsigned)__cvta_generic_to_shared(ks0);
    unsigned vs_base = (unsigned)__cvta_generic_to_shared(vs0);

    #pragma unroll
    for (int rep = 0; rep < 8; rep++) {
        int c = tid + rep * 64;
        int row = c >> 3, off = c & 7;
        cpasync16(ks_base + (row * SM_STRIDE + off * 8) * 2,
                  kg + (size_t)(it0 * 64 + row) * 64 + off * 8);
        cpasync16(vs_base + (row * SM_STRIDE + off * 8) * 2,
                  vg + (size_t)(it0 * 64 + row) * 64 + off * 8);
    }
    asm volatile("cp.async.commit_group;\n");

    asm volatile("griddepcontrol.launch_dependents;" ::: "memory");

    for (int c = tid; c < 512; c += 64) {
        int row = c >> 3, off = c & 7;
        *(uint4*)(qs + row * SM_STRIDE + off * 8) =
            *(const uint4*)(qg + (size_t)(m0 + row) * 64 + off * 8);
    }
    asm volatile("cp.async.wait_group 0;\n");
    __syncthreads();

    unsigned qa[2][4][4];
    #pragma unroll
    for (int s = 0; s < 2; s++) {
        int row = (w << 5) + (s << 4) + (lane & 15);
        #pragma unroll
        for (int kc = 0; kc < 4; kc++) {
            int dof = kc * 16 + (lane >> 4) * 8;
            ldm4(qa[s][kc], qs_base + (row * SM_STRIDE + dof) * 2);
        }
    }

    unsigned Ofh[2][8][2];       // f16x2 accumulators
    #pragma unroll
    for (int s = 0; s < 2; s++)
        #pragma unroll
        for (int dc = 0; dc < 8; dc++) {
            Ofh[s][dc][0] = 0u; Ofh[s][dc][1] = 0u;
        }
    float mrow[2][2], lrow[2][2];
    #pragma unroll
    for (int s = 0; s < 2; s++) {
        mrow[s][0] = -1e30f; mrow[s][1] = -1e30f;
        lrow[s][0] = 0.0f;   lrow[s][1] = 0.0f;
    }
    const unsigned ONES = 0x3C003C00u;

    for (int itr = 0; itr < 32; itr++) {
        int bf = itr & 1;
        unsigned ksb = ks_base + bf * 64 * SM_STRIDE * 2;
        unsigned vsb = vs_base + bf * 64 * SM_STRIDE * 2;

        if (itr + 1 < 32) {
            int n0n = (it0 + itr + 1) << 6;
            int nb  = (itr + 1) & 1;
            #pragma unroll
            for (int rep = 0; rep < 8; rep++) {
                int c = tid + rep * 64;
                int row = c >> 3, off = c & 7;
                cpasync16(ks_base + (nb * 64 * SM_STRIDE + row * SM_STRIDE + off * 8) * 2,
                          kg + (size_t)(n0n + row) * 64 + off * 8);
                cpasync16(vs_base + (nb * 64 * SM_STRIDE + row * SM_STRIDE + off * 8) * 2,
                          vg + (size_t)(n0n + row) * 64 + off * 8);
            }
            asm volatile("cp.async.commit_group;\n");
        }

        // S = Q @ K^T (f32 acc)
        float S[2][8][4];
        #pragma unroll
        for (int nc = 0; nc < 8; nc++) {
            unsigned kb[8];
            int krow = nc * 8 + (lane & 7);
            int kd   = (lane >> 3) * 8;
            ldm4(kb,     ksb + (krow * SM_STRIDE + kd) * 2);
            ldm4(kb + 4, ksb + (krow * SM_STRIDE + 32 + kd) * 2);
            #pragma unroll
            for (int s = 0; s < 2; s++) {
                #pragma unroll
                for (int q = 0; q < 4; q++) S[s][nc][q] = 0.0f;
                mma16816(S[s][nc], qa[s][0][0], qa[s][0][1], qa[s][0][2], qa[s][0][3], kb[0], kb[1]);
                mma16816(S[s][nc], qa[s][1][0], qa[s][1][1], qa[s][1][2], qa[s][1][3], kb[2], kb[3]);
                mma16816(S[s][nc], qa[s][2][0], qa[s][2][1], qa[s][2][2], qa[s][2][3], kb[4], kb[5]);
                mma16816(S[s][nc], qa[s][3][0], qa[s][3][1], qa[s][3][2], qa[s][3][3], kb[6], kb[7]);
            }
        }

        unsigned P[2][4][4];
        #pragma unroll
        for (int s = 0; s < 2; s++) {
            float tm0 = fmaxf(S[s][0][0], S[s][0][1]);
            float tm1 = fmaxf(S[s][0][2], S[s][0][3]);
            #pragma unroll
            for (int nc = 1; nc < 8; nc++) {
                tm0 = fmaxf(tm0, fmaxf(S[s][nc][0], S[s][nc][1]));
                tm1 = fmaxf(tm1, fmaxf(S[s][nc][2], S[s][nc][3]));
            }
            tm0 = fmaxf(tm0, __shfl_xor_sync(0xffffffffu, tm0, 1));
            tm0 = fmaxf(tm0, __shfl_xor_sync(0xffffffffu, tm0, 2));
            tm1 = fmaxf(tm1, __shfl_xor_sync(0xffffffffu, tm1, 1));
            tm1 = fmaxf(tm1, __shfl_xor_sync(0xffffffffu, tm1, 2));
            float nm0 = fmaxf(mrow[s][0], tm0), nm1 = fmaxf(mrow[s][1], tm1);
            float sc0 = exp2f((mrow[s][0] - nm0) * 1.44269504f);
            float sc1 = exp2f((mrow[s][1] - nm1) * 1.44269504f);
            mrow[s][0] = nm0; mrow[s][1] = nm1;
            float c0 = 1064866805.0f - nm0 * 12102203.16f;
            float c1 = 1064866805.0f - nm1 * 12102203.16f;

            #pragma unroll
            for (int jc = 0; jc < 4; jc++) {
                P[s][jc][0] = packh2(sexp(S[s][2*jc][0],   c0), sexp(S[s][2*jc][1],   c0));
                P[s][jc][1] = packh2(sexp(S[s][2*jc][2],   c1), sexp(S[s][2*jc][3],   c1));
                P[s][jc][2] = packh2(sexp(S[s][2*jc+1][0], c0), sexp(S[s][2*jc+1][1], c0));
                P[s][jc][3] = packh2(sexp(S[s][2*jc+1][2], c1), sexp(S[s][2*jc+1][3], c1));
            }

            unsigned lf[2] = {0u, 0u};
            #pragma unroll
            for (int jc = 0; jc < 4; jc++)
                mma16816h(lf, P[s][jc][0], P[s][jc][1], P[s][jc][2], P[s][jc][3], ONES, ONES);
            __half2 l0h = *(__half2*)&lf[0];
            __half2 l1h = *(__half2*)&lf[1];
            lrow[s][0] = lrow[s][0] * sc0 + __low2float(l0h);
            lrow[s][1] = lrow[s][1] * sc1 + __low2float(l1h);

            __half2 hs0 = __float2half2_rn(sc0);
            __half2 hs1 = __float2half2_rn(sc1);
            #pragma unroll
            for (int dc = 0; dc < 8; dc++) {
                __half2 a0 = *(__half2*)&Ofh[s][dc][0];
                __half2 a1 = *(__half2*)&Ofh[s][dc][1];
                a0 = __hmul2(a0, hs0);
                a1 = __hmul2(a1, hs1);
                Ofh[s][dc][0] = *(unsigned*)&a0;
                Ofh[s][dc][1] = *(unsigned*)&a1;
            }
        }

        // O += P @ V (f16 acc)
        #pragma unroll
        for (int jc = 0; jc < 4; jc++) {
            int vrow = jc * 16 + (lane & 15);
            int vcb  = (lane >> 4) * 8;
            #pragma unroll
            for (int dcp = 0; dcp < 4; dcp++) {
                unsigned vb[4];
                ldm4t(vb, vsb + (vrow * SM_STRIDE + dcp * 16 + vcb) * 2);
                #pragma unroll
                for (int s = 0; s < 2; s++) {
                    mma16816h(Ofh[s][2*dcp],     P[s][jc][0], P[s][jc][1], P[s][jc][2], P[s][jc][3], vb[0], vb[1]);
                    mma16816h(Ofh[s][2*dcp + 1], P[s][jc][0], P[s][jc][1], P[s][jc][2], P[s][jc][3], vb[2], vb[3]);
                }
            }
        }

        if (itr + 1 < 32) {
            asm volatile("cp.async.wait_group 0;\n");
            __syncthreads();
        }
    }

    float* Op = g_Op + (size_t)split * BATCH * CHN * NDS;
    #pragma unroll
    for (int s = 0; s < 2; s++) {
        int m = m0 + (w << 5) + (s << 4) + gid;
        #pragma unroll
        for (int dc = 0; dc < 8; dc++) {
            int d0 = dc * 8 + tig * 2;
            __half2 v0 = *(__half2*)&Ofh[s][dc][0];
            __half2 v1 = *(__half2*)&Ofh[s][dc][1];
            Op[(b * 64 + d0)     * NDS + m]     = __low2float(v0);
            Op[(b * 64 + d0 + 1) * NDS + m]     = __high2float(v0);
            Op[(b * 64 + d0)     * NDS + m + 8] = __low2float(v1);
            Op[(b * 64 + d0 + 1) * NDS + m + 8] = __high2float(v1);
        }
        if (tig == 0) {
            float* ml = g_ml + (size_t)((split * BATCH + b) * 2) * NDS;
            ml[m]           = mrow[s][0];
            ml[m + 8]       = mrow[s][1];
            ml[NDS + m]     = lrow[s][0];
            ml[NDS + m + 8] = lrow[s][1];
        }
    }
}

// ============================================================================
// K4: convout — round-12 config (128 threads, 128-px tiles, 76KB smem:
// co-resides with attn under PDL). Fused split-KV combine + epilogue,
// stride-36 overlay (144B rows, 16B-aligned).
// ============================================================================
#define CO_OFF_WH  0
#define CO_OFF_WL  25600
#define CO_OFF_STG 51200
#define CO_STG_BUF 8192
#define CO_OFF_ACT 67584
#define CO_ACT_BUF 4352
#define CONVOUT_SMEM 76288

__device__ __forceinline__ void co_issue_stage(
    const float* __restrict__ x1, const float* __restrict__ x2,
    int b, int p0, int t, unsigned dstbase, int ks)
{
    #pragma unroll
    for (int rep = 0; rep < 4; rep++) {
        int i = t + rep * 128;
        int row = i >> 5, off = i & 31;
        int c = ks * 16 + row;
        const float* src = (c < 128) ? x1 + (size_t)(b * 128 + c) * HW
                                     : x2 + (size_t)(b * 64 + c - 128) * HW;
        cpasync16(dstbase + row * 512 + off * 16, src + p0 + off * 4);
    }
    asm volatile("cp.async.commit_group;\n");
}

__device__ __forceinline__ void co_convert(const float* stg, __half* AH, int t)
{
    #pragma unroll
    for (int ch = 0; ch < 4; ch++) {
        int i = ch * 512 + t * 4;
        int row = i >> 7, col = i & 127;
        float4 v = *(const float4*)(stg + i);
        __half2 h0 = __floats2half2_rn(v.x, v.y);
        __half2 h1 = __floats2half2_rn(v.z, v.w);
        uint2 u;
        u.x = *(unsigned*)&h0;
        u.y = *(unsigned*)&h1;
        *(uint2*)&AH[row * 136 + col] = u;
    }
}

__global__ __launch_bounds__(128) void convout_kernel(
    const float* __restrict__ x1, const float* __restrict__ x2,
    const float* __restrict__ bias,
    const float* __restrict__ gamma, float* __restrict__ out)
{
    extern __shared__ char smc[];
    unsigned smu = (unsigned)__cvta_generic_to_shared(smc);

    int t = threadIdx.x;
    int lane = t & 31, wp = t >> 5;
    int ln15 = lane & 15, hb8 = (lane >> 4) * 8;
    int bx = blockIdx.x, b = blockIdx.y;
    int y = bx >> 1, xh = bx & 1;
    int p0 = (y << 8) + (xh << 7);
    int ndbase = ((y >> 2) << 6) + (xh << 5);

    #pragma unroll
    for (int rep = 0; rep < 13; rep++) {
        int i = t + rep * 128;
        if (i < 1600) {
            cpasync16(smu + CO_OFF_WH + i * 16, (const char*)g_wh + i * 16);
            cpasync16(smu + CO_OFF_WL + i * 16, (const char*)g_wl + i * 16);
        }
    }
    co_issue_stage(x1, x2, b, p0, t, smu + CO_OFF_STG, 0);
    co_issue_stage(x1, x2, b, p0, t, smu + CO_OFF_STG + CO_STG_BUF, 1);

    asm volatile("cp.async.wait_group 1;\n");
    __syncthreads();
    co_convert((const float*)(smc + CO_OFF_STG), (__half*)(smc + CO_OFF_ACT), t);

    float acc[4][4][4];
    #pragma unroll
    for (int mt = 0; mt < 4; mt++)
        #pragma unroll
        for (int nb = 0; nb < 4; nb++)
            #pragma unroll
            for (int q = 0; q < 4; q++) acc[mt][nb][q] = 0.0f;

    unsigned whB = smu + CO_OFF_WH + (ln15 * 200 + hb8) * 2;
    unsigned wlB = smu + CO_OFF_WL + (ln15 * 200 + hb8) * 2;

    #pragma unroll 1
    for (int ks = 0; ks < 12; ks++) {
        __syncthreads();
        if (ks + 2 < 12)
            co_issue_stage(x1, x2, b, p0, t,
                           smu + CO_OFF_STG + (ks & 1) * CO_STG_BUF, ks + 2);

        unsigned actH = smu + CO_OFF_ACT + (ks & 1) * CO_ACT_BUF +
                        (ln15 * 136 + wp * 32 + hb8) * 2;
        unsigned Bh[8], A[4][4];
        ldm4t(Bh,     actH);
        ldm4t(Bh + 4, actH + 32);
        #pragma unroll
        for (int mt = 0; mt < 4; mt++)
            ldm4(A[mt], whB + mt * 6400 + ks * 32);
        #pragma unroll
        for (int mt = 0; mt < 4; mt++) {
            mma16816(acc[mt][0], A[mt][0], A[mt][1], A[mt][2], A[mt][3], Bh[0], Bh[1]);
            mma16816(acc[mt][1], A[mt][0], A[mt][1], A[mt][2], A[mt][3], Bh[2], Bh[3]);
            mma16816(acc[mt][2], A[mt][0], A[mt][1], A[mt][2], A[mt][3], Bh[4], Bh[5]);
            mma16816(acc[mt][3], A[mt][0], A[mt][1], A[mt][2], A[mt][3], Bh[6], Bh[7]);
        }
        #pragma unroll
        for (int mt = 0; mt < 4; mt++)
            ldm4(A[mt], wlB + mt * 6400 + ks * 32);
        #pragma unroll
        for (int mt = 0; mt < 4; mt++) {
            mma16816(acc[mt][0], A[mt][0], A[mt][1], A[mt][2], A[mt][3], Bh[0], Bh[1]);
            mma16816(acc[mt][1], A[mt][0], A[mt][1], A[mt][2], A[mt][3], Bh[2], Bh[3]);
            mma16816(acc[mt][2], A[mt][0], A[mt][1], A[mt][2], A[mt][3], Bh[4], Bh[5]);
            mma16816(acc[mt][3], A[mt][0], A[mt][1], A[mt][2], A[mt][3], Bh[6], Bh[7]);
        }

        if (ks + 1 < 12) {
            if (ks + 2 < 12) { asm volatile("cp.async.wait_group 1;\n"); }
            else             { asm volatile("cp.async.wait_group 0;\n"); }
            co_convert((const float*)(smc + CO_OFF_STG + ((ks + 1) & 1) * CO_STG_BUF),
                       (__half*)(smc + CO_OFF_ACT + ((ks + 1) & 1) * CO_ACT_BUF), t);
        }
    }

    // wait for attn, then fused combine + epilogue
    asm volatile("griddepcontrol.wait;" ::: "memory");
    __syncthreads();

    float* OS  = (float*)(smc + CO_OFF_STG);       // [64][36] combined O
    float* ES  = OS + 64 * 36;                     // [64][36] ef
    float* SS0 = ES + 64 * 36;                     // [32]
    float* SS1 = SS0 + 32;

    if (t < 32) {
        int nd = ndbase + t;
        float m0 = g_ml[(size_t)((0 * BATCH + b) * 2) * NDS + nd];
        float l0 = g_ml[(size_t)((0 * BATCH + b) * 2) * NDS + NDS + nd];
        float m1 = g_ml[(size_t)((1 * BATCH + b) * 2) * NDS + nd];
        float l1 = g_ml[(size_t)((1 * BATCH + b) * 2) * NDS + NDS + nd];
        float M  = fmaxf(m0, m1);
        float s0 = exp2f((m0 - M) * 1.44269504f);
        float s1 = exp2f((m1 - M) * 1.44269504f);
        float inv = 1.0f / (l0 * s0 + l1 * s1);
        SS0[t] = s0 * inv;
        SS1[t] = s1 * inv;
    }
    __syncthreads();

    {
        int o = t >> 1, c0 = (t & 1) << 4;
        const float* po0 = g_Op + (size_t)(b * 64 + o) * NDS + ndbase + c0;
        const float* po1 = g_Op + (size_t)(BATCH * CHN + b * 64 + o) * NDS + ndbase + c0;
        const float* pe  = g_efd + (size_t)(b * 64 + o) * NDS + ndbase + c0;
        #pragma unroll
        for (int j = 0; j < 4; j++) {
            float4 a0 = *(const float4*)(po0 + 4 * j);
            float4 a1 = *(const float4*)(po1 + 4 * j);
            int cc = c0 + 4 * j;
            float4 r;
            r.x = a0.x * SS0[cc]     + a1.x * SS1[cc];
            r.y = a0.y * SS0[cc + 1] + a1.y * SS1[cc + 1];
            r.z = a0.z * SS0[cc + 2] + a1.z * SS1[cc + 2];
            r.w = a0.w * SS0[cc + 3] + a1.w * SS1[cc + 3];
            *(float4*)&OS[o * 36 + cc] = r;
            *(float4*)&ES[o * 36 + cc] = *(const float4*)(pe + 4 * j);
        }
    }
    __syncthreads();

    float tg = THITA_F * __ldg(gamma);
    int g = lane >> 2, tig = lane & 3;
    #pragma unroll
    for (int mt = 0; mt < 4; mt++) {
        int o = mt * 16 + g;
        float bb0 = __ldg(&bias[o]), bb1 = __ldg(&bias[o + 8]);
        #pragma unroll
        for (int nb = 0; nb < 4; nb++) {
            int pxl = wp * 32 + nb * 8 + tig * 2;
            int ndc = pxl >> 2;
            float a0 = tg * OS[o * 36 + ndc];
            float a1 = tg * OS[(o + 8) * 36 + ndc];
            float2 r0 = make_float2(fmaxf(acc[mt][nb][0] + bb0, 0.0f) + a0,
                                    fmaxf(acc[mt][nb][1] + bb0, 0.0f) + a0);
            float2 r1 = make_float2(fmaxf(acc[mt][nb][2] + bb1, 0.0f) + a1,
                                    fmaxf(acc[mt][nb][3] + bb1, 0.0f) + a1);
            *(float2*)(out + (size_t)(b * 64 + o)     * HW + p0 + pxl) = r0;
            *(float2*)(out + (size_t)(b * 64 + o + 8) * HW + p0 + pxl) = r1;
        }
    }

    int xq = t & 31, oo = t >> 5;
    #pragma unroll
    for (int rep = 0; rep < 16; rep++) {
        int o = rep * 4 + oo;
        float v = ES[o * 36 + xq];
        *(float4*)(out + OUT2OFF + (size_t)(b * 64 + o) * HW + p0 + (xq << 2)) =
            make_float4(v, v, v, v);
    }
}

// ============================================================================
extern "C" void kernel_launch(void* const* d_in, const int* in_sizes, int n_in,
                              void* d_out, int out_size)
{
    const float* x1    = (const float*)d_in[0];
    const float* x2    = (const float*)d_in[1];
    const float* ev    = (const float*)d_in[2];
    const float* xw0   = (const float*)d_in[3];
    const float* xb0   = (const float*)d_in[4];
    const float* xw1   = (const float*)d_in[5];
    const float* xb1   = (const float*)d_in[6];
    const float* ew0   = (const float*)d_in[7];
    const float* eb0   = (const float*)d_in[8];
    const float* ew1   = (const float*)d_in[9];
    const float* eb1   = (const float*)d_in[10];
    const float* qw    = (const float*)d_in[11];
    const float* qb    = (const float*)d_in[12];
    const float* kw    = (const float*)d_in[13];
    const float* kb    = (const float*)d_in[14];
    const float* vw    = (const float*)d_in[15];
    const float* vb    = (const float*)d_in[16];
    const float* gamma = (const float*)d_in[17];
    float* out = (float*)d_out;

    cudaFuncSetAttribute(prep_kernel,
                         cudaFuncAttributeMaxDynamicSharedMemorySize, PREP_SMEM);
    cudaFuncSetAttribute(qkv_kernel,
                         cudaFuncAttributeMaxDynamicSharedMemorySize, QKV_SMEM);
    cudaFuncSetAttribute(attn_kernel,
                         cudaFuncAttributeMaxDynamicSharedMemorySize, ATTN_SMEM);
    cudaFuncSetAttribute(convout_kernel,
                         cudaFuncAttributeMaxDynamicSharedMemorySize, CONVOUT_SMEM);

    wconv_kernel<<<48, 256>>>(xw0);
    prep_kernel<<<dim3(NDS / 64, BATCH, 2), 128, PREP_SMEM>>>(
        x1, x2, ev, xw0, xb0, ew0, eb0, ew1, eb1);
    qkv_kernel<<<dim3(NDS / 64, BATCH), 128, QKV_SMEM>>>(
        xw1, xb1, qw, qb, kw, kb, vw, vb);
    attn_kernel<<<dim3(NDS / 64, BATCH, 2), 64, ATTN_SMEM>>>();

    // convout: PDL secondary — mainloop overlaps attn; epilogue (fused
    // split-KV combine + add + ef_up) gated on griddepcontrol.wait.
    {
        cudaLaunchConfig_t cfg = {};
        cfg.gridDim = dim3(512, BATCH, 1);
        cfg.blockDim = dim3(128, 1, 1);
        cfg.dynamicSmemBytes = CONVOUT_SMEM;
        cfg.stream = 0;
        cudaLaunchAttribute attrs[1];
        attrs[0].id = cudaLaunchAttributeProgrammaticStreamSerialization;
        attrs[0].val.programmaticStreamSerializationAllowed = 1;
        cfg.attrs = attrs;
        cfg.numAttrs = 1;
        cudaLaunchKernelEx(&cfg, convout_kernel, x1, x2, xb0, gamma, out);
    }
}

// round 16
// speedup vs baseline: 1.1551x; 1.0670x over previous
#include <cuda_runtime.h>
#include <cuda_fp16.h>
#include <math.h>

#define BATCH 4
#define CHN 64
#define HW 65536        // 256*256
#define NDS 4096        // 64*64 downsampled pixels
#define THITA_F 1.0e-4f
#define OUT2OFF (BATCH * CHN * HW)

// ---------------- scratch (device globals) ----------------------------------
__device__ __half g_xdsh[BATCH * CHN * NDS];    // down4(x) f16 [b][c][n]
__device__ float  g_efd [BATCH * CHN * NDS];    // ef ds fp32 [b][c][n]
__device__ __half g_efdh[BATCH * CHN * NDS];    // ef ds f16
__device__ __half g_qh[BATCH * NDS * CHN];      // [b][n][d] f16
__device__ __half g_kh[BATCH * NDS * CHN];
__device__ __half g_vh[BATCH * NDS * CHN];
__device__ float  g_Op[2 * BATCH * CHN * NDS];  // split-KV partial O (unnormalized)
__device__ float  g_ml[2 * BATCH * 2 * NDS];    // split-KV per-row m and l
__device__ __half g_wh[64 * 200];               // conv0 weights f16 hi

// ============================================================================
// mma / ldmatrix helpers
// ============================================================================
__device__ __forceinline__ void mma16816(float* d,
    unsigned a0, unsigned a1, unsigned a2, unsigned a3,
    unsigned b0, unsigned b1)
{
    asm volatile(
        "mma.sync.aligned.m16n8k16.row.col.f32.f16.f16.f32 "
        "{%0,%1,%2,%3}, {%4,%5,%6,%7}, {%8,%9}, {%0,%1,%2,%3};\n"
        : "+f"(d[0]), "+f"(d[1]), "+f"(d[2]), "+f"(d[3])
        : "r"(a0), "r"(a1), "r"(a2), "r"(a3), "r"(b0), "r"(b1));
}
__device__ __forceinline__ void mma16816h(unsigned* d,
    unsigned a0, unsigned a1, unsigned a2, unsigned a3,
    unsigned b0, unsigned b1)
{
    asm volatile(
        "mma.sync.aligned.m16n8k16.row.col.f16.f16.f16.f16 "
        "{%0,%1}, {%2,%3,%4,%5}, {%6,%7}, {%0,%1};\n"
        : "+r"(d[0]), "+r"(d[1])
        : "r"(a0), "r"(a1), "r"(a2), "r"(a3), "r"(b0), "r"(b1));
}
__device__ __forceinline__ void ldm4(unsigned* r, unsigned a) {
    asm volatile("ldmatrix.sync.aligned.m8n8.x4.shared.b16 {%0,%1,%2,%3}, [%4];\n"
        : "=r"(r[0]), "=r"(r[1]), "=r"(r[2]), "=r"(r[3]) : "r"(a));
}
__device__ __forceinline__ void ldm4t(unsigned* r, unsigned a) {
    asm volatile("ldmatrix.sync.aligned.m8n8.x4.trans.shared.b16 {%0,%1,%2,%3}, [%4];\n"
        : "=r"(r[0]), "=r"(r[1]), "=r"(r[2]), "=r"(r[3]) : "r"(a));
}
__device__ __forceinline__ void cpasync16(unsigned dst, const void* src) {
    asm volatile("cp.async.cg.shared.global [%0], [%1], 16;\n"
        :: "r"(dst), "l"(src));
}
__device__ __forceinline__ unsigned hpack(__half a, __half b) {
    __half2 h = __halves2half2(a, b);
    return *(unsigned*)&h;
}
__device__ __forceinline__ unsigned packh2(float a, float b) {
    __half2 h = __floats2half2_rn(a, b);
    return *(unsigned*)&h;
}
__device__ __forceinline__ float sexp(float s, float c) {
    float t = fmaf(s, 12102203.16f, c);
    t = fmaxf(t, 0.0f);
    return __int_as_float(__float2int_rn(t));
}

// single-pass f16 GEMM
__device__ __forceinline__ void gemm1p(float acc[8][4], unsigned wb, int wstride,
                                       unsigned ab, int nks, int lane)
{
    int ln15 = lane & 15, hb8 = (lane >> 4) * 8;
    unsigned wl = wb + (ln15 * wstride + hb8) * 2;
    #pragma unroll
    for (int ks = 0; ks < nks; ks++) {
        unsigned al = ab + ((ks * 16 + ln15) * 72 + hb8) * 2;
        unsigned B[16], A[4];
        ldm4t(B,      al);
        ldm4t(B + 4,  al + 32);
        ldm4t(B + 8,  al + 64);
        ldm4t(B + 12, al + 96);
        ldm4(A, wl + ks * 32);
        #pragma unroll
        for (int nc = 0; nc < 8; nc++) {
            int ib = (nc >> 1) * 4 + (nc & 1) * 2;
            mma16816(acc[nc], A[0], A[1], A[2], A[3], B[ib], B[ib + 1]);
        }
    }
}

// 3-pass hi/lo GEMM (K=64)
__device__ __forceinline__ void gemm3p(float acc[8][4],
    unsigned wh, unsigned wlo, unsigned ah, unsigned alo, int lane)
{
    int ln15 = lane & 15, hb8 = (lane >> 4) * 8;
    unsigned wbh = wh  + (ln15 * 72 + hb8) * 2;
    unsigned wbl = wlo + (ln15 * 72 + hb8) * 2;
    #pragma unroll
    for (int ks = 0; ks < 4; ks++) {
        unsigned abh = ah  + ((ks * 16 + ln15) * 72 + hb8) * 2;
        unsigned abl = alo + ((ks * 16 + ln15) * 72 + hb8) * 2;
        unsigned Bh[16], Bl[16], Wf[4], Lf[4];
        ldm4t(Bh,      abh);
        ldm4t(Bh + 4,  abh + 32);
        ldm4t(Bh + 8,  abh + 64);
        ldm4t(Bh + 12, abh + 96);
        ldm4t(Bl,      abl);
        ldm4t(Bl + 4,  abl + 32);
        ldm4t(Bl + 8,  abl + 64);
        ldm4t(Bl + 12, abl + 96);
        ldm4(Wf, wbh + ks * 32);
        ldm4(Lf, wbl + ks * 32);
        #pragma unroll
        for (int nc = 0; nc < 8; nc++) {
            int ib = (nc >> 1) * 4 + (nc & 1) * 2;
            mma16816(acc[nc], Wf[0], Wf[1], Wf[2], Wf[3], Bh[ib], Bh[ib + 1]);
            mma16816(acc[nc], Wf[0], Wf[1], Wf[2], Wf[3], Bl[ib], Bl[ib + 1]);
            mma16816(acc[nc], Lf[0], Lf[1], Lf[2], Lf[3], Bh[ib], Bh[ib + 1]);
        }
    }
}

// ============================================================================
// K0: wconv — f16-hi conv0 weights
// ============================================================================
__global__ void wconv_kernel(const float* __restrict__ w)
{
    int i = blockIdx.x * 256 + threadIdx.x;
    if (i < 12288) {
        int o = i / 192, c = i - o * 192;
        g_wh[o * 200 + c] = __float2half_rn(w[i]);
    }
}

// ============================================================================
// K1: prep — z=0: conv0_ds (f16 1-pass) -> g_xdsh; z=1: ef chain (3-pass)
// ============================================================================
#define PREP_SMEM (64 * 200 * 2 + 192 * 72 * 2)

__global__ __launch_bounds__(128) void prep_kernel(
    const float* __restrict__ x1, const float* __restrict__ x2,
    const float* __restrict__ ev,
    const float* __restrict__ xw0, const float* __restrict__ xb0,
    const float* __restrict__ ew0, const float* __restrict__ eb0,
    const float* __restrict__ ew1, const float* __restrict__ eb1)
{
    extern __shared__ char smc[];
    unsigned smu = (unsigned)__cvta_generic_to_shared(smc);
    int t = threadIdx.x, lane = t & 31, w = t >> 5;
    int gid = lane >> 2, tig = lane & 3;
    int blk = blockIdx.x, b = blockIdx.y;
    int n0 = blk << 6;

    float acc[8][4];
    #pragma unroll
    for (int nc = 0; nc < 8; nc++)
        #pragma unroll
        for (int q = 0; q < 4; q++) acc[nc][q] = 0.0f;

    if (blockIdx.z == 0) {
        __half* W  = (__half*)smc;
        __half* Ac = (__half*)(smc + 64 * 200 * 2);
        for (int i = t; i < 12288; i += 128) {
            int o = i / 192, c = i - o * 192;
            W[o * 200 + c] = __float2half_rn(xw0[i]);
        }
        for (int i = t; i < 12288; i += 128) {
            int c = i >> 6, x = i & 63;
            const float* s = (c < 128) ? x1 + (size_t)(b * 128 + c) * HW
                                       : x2 + (size_t)(b * 64 + c - 128) * HW;
            Ac[c * 72 + x] = __float2half_rn(s[(blk << 10) + (x << 2)]);
        }
        __syncthreads();

        gemm1p(acc, smu + (w * 16) * 200 * 2, 200,
               smu + 64 * 200 * 2, 12, lane);

        int o = (w << 4) + gid;
        float b0 = __ldg(&xb0[o]), b1 = __ldg(&xb0[o + 8]);
        #pragma unroll
        for (int nc = 0; nc < 8; nc++) {
            int n = n0 + nc * 8 + tig * 2;
            *(__half2*)&g_xdsh[(size_t)(b * 64 + o) * NDS + n] =
                __floats2half2_rn(fmaxf(acc[nc][0] + b0, 0.0f),
                                  fmaxf(acc[nc][1] + b0, 0.0f));
            *(__half2*)&g_xdsh[(size_t)(b * 64 + o + 8) * NDS + n] =
                __floats2half2_rn(fmaxf(acc[nc][2] + b1, 0.0f),
                                  fmaxf(acc[nc][3] + b1, 0.0f));
        }
    } else {
        __half* Wh = (__half*)smc;
        __half* Wl = Wh + 64 * 72;
        __half* Ah = Wl + 64 * 72;
        __half* Al = Ah + 64 * 72;
        unsigned oWh = smu, oWl = smu + 9216, oAh = smu + 18432, oAl = smu + 27648;

        for (int i = t; i < 4096; i += 128) {
            float v = ew0[i];
            __half h = __float2half_rn(v);
            int o = i >> 6, c = i & 63;
            Wh[o * 72 + c] = h;
            Wl[o * 72 + c] = __float2half_rn(v - __half2float(h));
        }
        for (int i = t; i < 4096; i += 128) {
            int c = i >> 6, x = i & 63;
            float v = ev[(size_t)(b * 64 + c) * HW + (blk << 10) + (x << 2)];
            __half h = __float2half_rn(v);
            Ah[c * 72 + x] = h;
            Al[c * 72 + x] = __float2half_rn(v - __half2float(h));
        }
        __syncthreads();

        gemm3p(acc, oWh + (w * 16) * 144, oWl + (w * 16) * 144, oAh, oAl, lane);
        __syncthreads();

        {
            int o = (w << 4) + gid;
            float b0 = __ldg(&eb0[o]), b1 = __ldg(&eb0[o + 8]);
            #pragma unroll
            for (int nc = 0; nc < 8; nc++) {
                int px = nc * 8 + tig * 2;
                float t0 = fmaxf(acc[nc][0] + b0, 0.0f);
                float t1 = fmaxf(acc[nc][1] + b0, 0.0f);
                float t2 = fmaxf(acc[nc][2] + b1, 0.0f);
                float t3 = fmaxf(acc[nc][3] + b1, 0.0f);
                __half h0 = __float2half_rn(t0), h1 = __float2half_rn(t1);
                __half h2 = __float2half_rn(t2), h3 = __float2half_rn(t3);
                *(__half2*)&Ah[o * 72 + px] = __halves2half2(h0, h1);
                *(__half2*)&Al[o * 72 + px] = __floats2half2_rn(
                    t0 - __half2float(h0), t1 - __half2float(h1));
                *(__half2*)&Ah[(o + 8) * 72 + px] = __halves2half2(h2, h3);
                *(__half2*)&Al[(o + 8) * 72 + px] = __floats2half2_rn(
                    t2 - __half2float(h2), t3 - __half2float(h3));
            }
        }
        for (int i = t; i < 4096; i += 128) {
            float v = ew1[i];
            __half h = __float2half_rn(v);
            int o = i >> 6, c = i & 63;
            Wh[o * 72 + c] = h;
            Wl[o * 72 + c] = __float2half_rn(v - __half2float(h));
        }
        __syncthreads();

        #pragma unroll
        for (int nc = 0; nc < 8; nc++)
            #pragma unroll
            for (int q = 0; q < 4; q++) acc[nc][q] = 0.0f;
        gemm3p(acc, oWh + (w * 16) * 144, oWl + (w * 16) * 144, oAh, oAl, lane);

        int o = (w << 4) + gid;
        float b0 = __ldg(&eb1[o]), b1 = __ldg(&eb1[o + 8]);
        #pragma unroll
        for (int nc = 0; nc < 8; nc++) {
            int n = n0 + nc * 8 + tig * 2;
            float r0 = fmaxf(acc[nc][0] + b0, 0.0f);
            float r1 = fmaxf(acc[nc][1] + b0, 0.0f);
            float r2 = fmaxf(acc[nc][2] + b1, 0.0f);
            float r3 = fmaxf(acc[nc][3] + b1, 0.0f);
            *(float2*)&g_efd[(size_t)(b * 64 + o) * NDS + n]     = make_float2(r0, r1);
            *(float2*)&g_efd[(size_t)(b * 64 + o + 8) * NDS + n] = make_float2(r2, r3);
            *(__half2*)&g_efdh[(size_t)(b * 64 + o) * NDS + n]     = __floats2half2_rn(r0, r1);
            *(__half2*)&g_efdh[(size_t)(b * 64 + o + 8) * NDS + n] = __floats2half2_rn(r2, r3);
        }
    }
}

// ============================================================================
// K2: qkv — all f16 1-pass mma (unchanged)
// ============================================================================
#define QKV_SMEM (4 * 64 * 72 * 2)

__global__ __launch_bounds__(128) void qkv_kernel(
    const float* __restrict__ xw1, const float* __restrict__ xb1,
    const float* __restrict__ qw,  const float* __restrict__ qb,
    const float* __restrict__ kw,  const float* __restrict__ kb,
    const float* __restrict__ vw,  const float* __restrict__ vb)
{
    extern __shared__ char smc[];
    unsigned smu = (unsigned)__cvta_generic_to_shared(smc);
    __half* W   = (__half*)smc;
    __half* Act = W + 64 * 72;
    __half* Tb  = Act + 64 * 72;
    __half* Tr  = Tb + 64 * 72;
    unsigned oW = smu, oAct = smu + 9216, oTb = smu + 18432;

    int t = threadIdx.x, lane = t & 31, w = t >> 5;
    int gid = lane >> 2, tig = lane & 3;
    int blk = blockIdx.x, b = blockIdx.y;
    int n0 = blk << 6;
    int o = (w << 4) + gid;

    for (int i = t; i < 512; i += 128) {
        int row = i >> 3, off = i & 7;
        *(uint4*)&Act[row * 72 + off * 8] =
            *(const uint4*)&g_xdsh[(size_t)(b * 64 + row) * NDS + n0 + off * 8];
    }
    for (int i = t; i < 4096; i += 128)
        W[(i >> 6) * 72 + (i & 63)] = __float2half_rn(xw1[i]);
    __syncthreads();

    float acc[8][4];
    #pragma unroll
    for (int nc = 0; nc < 8; nc++)
        #pragma unroll
        for (int q = 0; q < 4; q++) acc[nc][q] = 0.0f;
    gemm1p(acc, oW + (w * 16) * 144, 72, oAct, 4, lane);
    {
        float b0 = __ldg(&xb1[o]), b1 = __ldg(&xb1[o + 8]);
        #pragma unroll
        for (int nc = 0; nc < 8; nc++) {
            int px = nc * 8 + tig * 2;
            *(__half2*)&Tb[o * 72 + px] = __floats2half2_rn(
                fmaxf(acc[nc][0] + b0, 0.0f), fmaxf(acc[nc][1] + b0, 0.0f));
            *(__half2*)&Tb[(o + 8) * 72 + px] = __floats2half2_rn(
                fmaxf(acc[nc][2] + b1, 0.0f), fmaxf(acc[nc][3] + b1, 0.0f));
        }
    }
    __syncthreads();
    for (int i = t; i < 4096; i += 128)
        W[(i >> 6) * 72 + (i & 63)] = __float2half_rn(qw[i]);
    __syncthreads();

    #pragma unroll
    for (int nc = 0; nc < 8; nc++)
        #pragma unroll
        for (int q = 0; q < 4; q++) acc[nc][q] = 0.0f;
    gemm1p(acc, oW + (w * 16) * 144, 72, oTb, 4, lane);
    {
        float b0 = __ldg(&qb[o]), b1 = __ldg(&qb[o + 8]);
        #pragma unroll
        for (int nc = 0; nc < 8; nc++) {
            int px = nc * 8 + tig * 2;
            Tr[px * 72 + o]           = __float2half_rn(fmaxf(acc[nc][0] + b0, 0.0f));
            Tr[(px + 1) * 72 + o]     = __float2half_rn(fmaxf(acc[nc][1] + b0, 0.0f));
            Tr[px * 72 + o + 8]       = __float2half_rn(fmaxf(acc[nc][2] + b1, 0.0f));
            Tr[(px + 1) * 72 + o + 8] = __float2half_rn(fmaxf(acc[nc][3] + b1, 0.0f));
        }
    }
    __syncthreads();
    for (int i = t; i < 512; i += 128) {
        int row = i >> 3, off = i & 7;
        *(uint4*)&g_qh[((size_t)b * NDS + n0 + row) * 64 + off * 8] =
            *(uint4*)&Tr[row * 72 + off * 8];
    }
    for (int i = t; i < 4096; i += 128)
        W[(i >> 6) * 72 + (i & 63)] = __float2half_rn(vw[i]);
    __syncthreads();

    #pragma unroll
    for (int nc = 0; nc < 8; nc++)
        #pragma unroll
        for (int q = 0; q < 4; q++) acc[nc][q] = 0.0f;
    gemm1p(acc, oW + (w * 16) * 144, 72, oTb, 4, lane);
    {
        float b0 = __ldg(&vb[o]), b1 = __ldg(&vb[o + 8]);
        #pragma unroll
        for (int nc = 0; nc < 8; nc++) {
            int px = nc * 8 + tig * 2;
            Tr[px * 72 + o]           = __float2half_rn(fmaxf(acc[nc][0] + b0, 0.0f));
            Tr[(px + 1) * 72 + o]     = __float2half_rn(fmaxf(acc[nc][1] + b0, 0.0f));
            Tr[px * 72 + o + 8]       = __float2half_rn(fmaxf(acc[nc][2] + b1, 0.0f));
            Tr[(px + 1) * 72 + o + 8] = __float2half_rn(fmaxf(acc[nc][3] + b1, 0.0f));
        }
    }
    __syncthreads();
    for (int i = t; i < 512; i += 128) {
        int row = i >> 3, off = i & 7;
        *(uint4*)&g_vh[((size_t)b * NDS + n0 + row) * 64 + off * 8] =
            *(uint4*)&Tr[row * 72 + off * 8];
    }
    for (int i = t; i < 4096; i += 128)
        W[(i >> 6) * 72 + (i & 63)] = __float2half_rn(kw[i]);
    for (int i = t; i < 512; i += 128) {
        int row = i >> 3, off = i & 7;
        *(uint4*)&Act[row * 72 + off * 8] =
            *(const uint4*)&g_efdh[(size_t)(b * 64 + row) * NDS + n0 + off * 8];
    }
    __syncthreads();

    #pragma unroll
    for (int nc = 0; nc < 8; nc++)
        #pragma unroll
        for (int q = 0; q < 4; q++) acc[nc][q] = 0.0f;
    gemm1p(acc, oW + (w * 16) * 144, 72, oAct, 4, lane);
    {
        float b0 = __ldg(&kb[o]), b1 = __ldg(&kb[o + 8]);
        #pragma unroll
        for (int nc = 0; nc < 8; nc++) {
            int px = nc * 8 + tig * 2;
            Tr[px * 72 + o]           = __float2half_rn(fmaxf(acc[nc][0] + b0, 0.0f));
            Tr[(px + 1) * 72 + o]     = __float2half_rn(fmaxf(acc[nc][1] + b0, 0.0f));
            Tr[px * 72 + o + 8]       = __float2half_rn(fmaxf(acc[nc][2] + b1, 0.0f));
            Tr[(px + 1) * 72 + o + 8] = __float2half_rn(fmaxf(acc[nc][3] + b1, 0.0f));
        }
    }
    __syncthreads();
    for (int i = t; i < 512; i += 128) {
        int row = i >> 3, off = i & 7;
        *(uint4*)&g_kh[((size_t)b * NDS + n0 + row) * 64 + off * 8] =
            *(uint4*)&Tr[row * 72 + off * 8];
    }
}

// ============================================================================
// K3: flash attention — split-KV x2, 64-thr CTAs, f16 PV accumulators.
// (64,3): cap 3 CTAs/SM (138 KB) so a 50.7 KB convout CTA co-resides.
// ============================================================================
#define SM_STRIDE 72
#define ATTN_SMEM ((64 * SM_STRIDE + 4 * 64 * SM_STRIDE) * 2)   // 46080

__global__ __launch_bounds__(64, 3) void attn_kernel()
{
    extern __shared__ __half smh[];
    __half* qs  = smh;
    __half* ks0 = smh + 64 * SM_STRIDE;
    __half* vs0 = ks0 + 2 * 64 * SM_STRIDE;

    int tid  = threadIdx.x;
    int lane = tid & 31, w = tid >> 5;
    int gid  = lane >> 2, tig = lane & 3;
    int b    = blockIdx.y;
    int m0   = blockIdx.x << 6;
    int split = blockIdx.z;
    int it0  = split << 5;

    const __half* qg = g_qh + (size_t)b * NDS * 64;
    const __half* kg = g_kh + (size_t)b * NDS * 64;
    const __half* vg = g_vh + (size_t)b * NDS * 64;

    unsigned qs_base = (unsigned)__cvta_generic_to_shared(qs);
    unsigned ks_base = (unsigned)__cvta_generic_to_shared(ks0);
    unsigned vs_base = (unsigned)__cvta_generic_to_shared(vs0);

    #pragma unroll
    for (int rep = 0; rep < 8; rep++) {
        int c = tid + rep * 64;
        int row = c >> 3, off = c & 7;
        cpasync16(ks_base + (row * SM_STRIDE + off * 8) * 2,
                  kg + (size_t)(it0 * 64 + row) * 64 + off * 8);
        cpasync16(vs_base + (row * SM_STRIDE + off * 8) * 2,
                  vg + (size_t)(it0 * 64 + row) * 64 + off * 8);
    }
    asm volatile("cp.async.commit_group;\n");

    asm volatile("griddepcontrol.launch_dependents;" ::: "memory");

    for (int c = tid; c < 512; c += 64) {
        int row = c >> 3, off = c & 7;
        *(uint4*)(qs + row * SM_STRIDE + off * 8) =
            *(const uint4*)(qg + (size_t)(m0 + row) * 64 + off * 8);
    }
    asm volatile("cp.async.wait_group 0;\n");
    __syncthreads();

    unsigned qa[2][4][4];
    #pragma unroll
    for (int s = 0; s < 2; s++) {
        int row = (w << 5) + (s << 4) + (lane & 15);
        #pragma unroll
        for (int kc = 0; kc < 4; kc++) {
            int dof = kc * 16 + (lane >> 4) * 8;
            ldm4(qa[s][kc], qs_base + (row * SM_STRIDE + dof) * 2);
        }
    }

    unsigned Ofh[2][8][2];
    #pragma unroll
    for (int s = 0; s < 2; s++)
        #pragma unroll
        for (int dc = 0; dc < 8; dc++) {
            Ofh[s][dc][0] = 0u; Ofh[s][dc][1] = 0u;
        }
    float mrow[2][2], lrow[2][2];
    #pragma unroll
    for (int s = 0; s < 2; s++) {
        mrow[s][0] = -1e30f; mrow[s][1] = -1e30f;
        lrow[s][0] = 0.0f;   lrow[s][1] = 0.0f;
    }
    const unsigned ONES = 0x3C003C00u;

    for (int itr = 0; itr < 32; itr++) {
        int bf = itr & 1;
        unsigned ksb = ks_base + bf * 64 * SM_STRIDE * 2;
        unsigned vsb = vs_base + bf * 64 * SM_STRIDE * 2;

        if (itr + 1 < 32) {
            int n0n = (it0 + itr + 1) << 6;
            int nb  = (itr + 1) & 1;
            #pragma unroll
            for (int rep = 0; rep < 8; rep++) {
                int c = tid + rep * 64;
                int row = c >> 3, off = c & 7;
                cpasync16(ks_base + (nb * 64 * SM_STRIDE + row * SM_STRIDE + off * 8) * 2,
                          kg + (size_t)(n0n + row) * 64 + off * 8);
                cpasync16(vs_base + (nb * 64 * SM_STRIDE + row * SM_STRIDE + off * 8) * 2,
                          vg + (size_t)(n0n + row) * 64 + off * 8);
            }
            asm volatile("cp.async.commit_group;\n");
        }

        float S[2][8][4];
        #pragma unroll
        for (int nc = 0; nc < 8; nc++) {
            unsigned kb[8];
            int krow = nc * 8 + (lane & 7);
            int kd   = (lane >> 3) * 8;
            ldm4(kb,     ksb + (krow * SM_STRIDE + kd) * 2);
            ldm4(kb + 4, ksb + (krow * SM_STRIDE + 32 + kd) * 2);
            #pragma unroll
            for (int s = 0; s < 2; s++) {
                #pragma unroll
                for (int q = 0; q < 4; q++) S[s][nc][q] = 0.0f;
                mma16816(S[s][nc], qa[s][0][0], qa[s][0][1], qa[s][0][2], qa[s][0][3], kb[0], kb[1]);
                mma16816(S[s][nc], qa[s][1][0], qa[s][1][1], qa[s][1][2], qa[s][1][3], kb[2], kb[3]);
                mma16816(S[s][nc], qa[s][2][0], qa[s][2][1], qa[s][2][2], qa[s][2][3], kb[4], kb[5]);
                mma16816(S[s][nc], qa[s][3][0], qa[s][3][1], qa[s][3][2], qa[s][3][3], kb[6], kb[7]);
            }
        }

        unsigned P[2][4][4];
        #pragma unroll
        for (int s = 0; s < 2; s++) {
            float tm0 = fmaxf(S[s][0][0], S[s][0][1]);
            float tm1 = fmaxf(S[s][0][2], S[s][0][3]);
            #pragma unroll
            for (int nc = 1; nc < 8; nc++) {
                tm0 = fmaxf(tm0, fmaxf(S[s][nc][0], S[s][nc][1]));
                tm1 = fmaxf(tm1, fmaxf(S[s][nc][2], S[s][nc][3]));
            }
            tm0 = fmaxf(tm0, __shfl_xor_sync(0xffffffffu, tm0, 1));
            tm0 = fmaxf(tm0, __shfl_xor_sync(0xffffffffu, tm0, 2));
            tm1 = fmaxf(tm1, __shfl_xor_sync(0xffffffffu, tm1, 1));
            tm1 = fmaxf(tm1, __shfl_xor_sync(0xffffffffu, tm1, 2));
            float nm0 = fmaxf(mrow[s][0], tm0), nm1 = fmaxf(mrow[s][1], tm1);
            float sc0 = exp2f((mrow[s][0] - nm0) * 1.44269504f);
            float sc1 = exp2f((mrow[s][1] - nm1) * 1.44269504f);
            mrow[s][0] = nm0; mrow[s][1] = nm1;
            float c0 = 1064866805.0f - nm0 * 12102203.16f;
            float c1 = 1064866805.0f - nm1 * 12102203.16f;

            #pragma unroll
            for (int jc = 0; jc < 4; jc++) {
                P[s][jc][0] = packh2(sexp(S[s][2*jc][0],   c0), sexp(S[s][2*jc][1],   c0));
                P[s][jc][1] = packh2(sexp(S[s][2*jc][2],   c1), sexp(S[s][2*jc][3],   c1));
                P[s][jc][2] = packh2(sexp(S[s][2*jc+1][0], c0), sexp(S[s][2*jc+1][1], c0));
                P[s][jc][3] = packh2(sexp(S[s][2*jc+1][2], c1), sexp(S[s][2*jc+1][3], c1));
            }

            unsigned lf[2] = {0u, 0u};
            #pragma unroll
            for (int jc = 0; jc < 4; jc++)
                mma16816h(lf, P[s][jc][0], P[s][jc][1], P[s][jc][2], P[s][jc][3], ONES, ONES);
            __half2 l0h = *(__half2*)&lf[0];
            __half2 l1h = *(__half2*)&lf[1];
            lrow[s][0] = lrow[s][0] * sc0 + __low2float(l0h);
            lrow[s][1] = lrow[s][1] * sc1 + __low2float(l1h);

            __half2 hs0 = __float2half2_rn(sc0);
            __half2 hs1 = __float2half2_rn(sc1);
            #pragma unroll
            for (int dc = 0; dc < 8; dc++) {
                __half2 a0 = *(__half2*)&Ofh[s][dc][0];
                __half2 a1 = *(__half2*)&Ofh[s][dc][1];
                a0 = __hmul2(a0, hs0);
                a1 = __hmul2(a1, hs1);
                Ofh[s][dc][0] = *(unsigned*)&a0;
                Ofh[s][dc][1] = *(unsigned*)&a1;
            }
        }

        #pragma unroll
        for (int jc = 0; jc < 4; jc++) {
            int vrow = jc * 16 + (lane & 15);
            int vcb  = (lane >> 4) * 8;
            #pragma unroll
            for (int dcp = 0; dcp < 4; dcp++) {
                unsigned vb[4];
                ldm4t(vb, vsb + (vrow * SM_STRIDE + dcp * 16 + vcb) * 2);
                #pragma unroll
                for (int s = 0; s < 2; s++) {
                    mma16816h(Ofh[s][2*dcp],     P[s][jc][0], P[s][jc][1], P[s][jc][2], P[s][jc][3], vb[0], vb[1]);
                    mma16816h(Ofh[s][2*dcp + 1], P[s][jc][0], P[s][jc][1], P[s][jc][2], P[s][jc][3], vb[2], vb[3]);
                }
            }
        }

        if (itr + 1 < 32) {
            asm volatile("cp.async.wait_group 0;\n");
            __syncthreads();
        }
    }

    float* Op = g_Op + (size_t)split * BATCH * CHN * NDS;
    #pragma unroll
    for (int s = 0; s < 2; s++) {
        int m = m0 + (w << 5) + (s << 4) + gid;
        #pragma unroll
        for (int dc = 0; dc < 8; dc++) {
            int d0 = dc * 8 + tig * 2;
            __half2 v0 = *(__half2*)&Ofh[s][dc][0];
            __half2 v1 = *(__half2*)&Ofh[s][dc][1];
            Op[(b * 64 + d0)     * NDS + m]     = __low2float(v0);
            Op[(b * 64 + d0 + 1) * NDS + m]     = __high2float(v0);
            Op[(b * 64 + d0)     * NDS + m + 8] = __low2float(v1);
            Op[(b * 64 + d0 + 1) * NDS + m + 8] = __high2float(v1);
        }
        if (tig == 0) {
            float* ml = g_ml + (size_t)((split * BATCH + b) * 2) * NDS;
            ml[m]           = mrow[s][0];
            ml[m + 8]       = mrow[s][1];
            ml[NDS + m]     = lrow[s][0];
            ml[NDS + m + 8] = lrow[s][1];
        }
    }
}

// ============================================================================
// K4: convout — ROUND 16: single weight pass (Wh only), smem 50.7 KB
// (4 CTAs/SM standalone; co-resides with attn(64,3) under PDL).
// Fused split-KV combine + epilogue, stride-36 overlay.
// ============================================================================
#define CO_OFF_WH  0
#define CO_OFF_STG 25600
#define CO_STG_BUF 8192
#define CO_OFF_ACT 41984
#define CO_ACT_BUF 4352
#define CONVOUT_SMEM 50688

__device__ __forceinline__ void co_issue_stage(
    const float* __restrict__ x1, const float* __restrict__ x2,
    int b, int p0, int t, unsigned dstbase, int ks)
{
    #pragma unroll
    for (int rep = 0; rep < 4; rep++) {
        int i = t + rep * 128;
        int row = i >> 5, off = i & 31;
        int c = ks * 16 + row;
        const float* src = (c < 128) ? x1 + (size_t)(b * 128 + c) * HW
                                     : x2 + (size_t)(b * 64 + c - 128) * HW;
        cpasync16(dstbase + row * 512 + off * 16, src + p0 + off * 4);
    }
    asm volatile("cp.async.commit_group;\n");
}

__device__ __forceinline__ void co_convert(const float* stg, __half* AH, int t)
{
    #pragma unroll
    for (int ch = 0; ch < 4; ch++) {
        int i = ch * 512 + t * 4;
        int row = i >> 7, col = i & 127;
        float4 v = *(const float4*)(stg + i);
        __half2 h0 = __floats2half2_rn(v.x, v.y);
        __half2 h1 = __floats2half2_rn(v.z, v.w);
        uint2 u;
        u.x = *(unsigned*)&h0;
        u.y = *(unsigned*)&h1;
        *(uint2*)&AH[row * 136 + col] = u;
    }
}

__global__ __launch_bounds__(128, 4) void convout_kernel(
    const float* __restrict__ x1, const float* __restrict__ x2,
    const float* __restrict__ bias,
    const float* __restrict__ gamma, float* __restrict__ out)
{
    extern __shared__ char smc[];
    unsigned smu = (unsigned)__cvta_generic_to_shared(smc);

    int t = threadIdx.x;
    int lane = t & 31, wp = t >> 5;
    int ln15 = lane & 15, hb8 = (lane >> 4) * 8;
    int bx = blockIdx.x, b = blockIdx.y;
    int y = bx >> 1, xh = bx & 1;
    int p0 = (y << 8) + (xh << 7);
    int ndbase = ((y >> 2) << 6) + (xh << 5);

    #pragma unroll
    for (int rep = 0; rep < 13; rep++) {
        int i = t + rep * 128;
        if (i < 1600)
            cpasync16(smu + CO_OFF_WH + i * 16, (const char*)g_wh + i * 16);
    }
    co_issue_stage(x1, x2, b, p0, t, smu + CO_OFF_STG, 0);
    co_issue_stage(x1, x2, b, p0, t, smu + CO_OFF_STG + CO_STG_BUF, 1);

    asm volatile("cp.async.wait_group 1;\n");
    __syncthreads();
    co_convert((const float*)(smc + CO_OFF_STG), (__half*)(smc + CO_OFF_ACT), t);

    float acc[4][4][4];
    #pragma unroll
    for (int mt = 0; mt < 4; mt++)
        #pragma unroll
        for (int nb = 0; nb < 4; nb++)
            #pragma unroll
            for (int q = 0; q < 4; q++) acc[mt][nb][q] = 0.0f;

    unsigned whB = smu + CO_OFF_WH + (ln15 * 200 + hb8) * 2;

    #pragma unroll 1
    for (int ks = 0; ks < 12; ks++) {
        __syncthreads();
        if (ks + 2 < 12)
            co_issue_stage(x1, x2, b, p0, t,
                           smu + CO_OFF_STG + (ks & 1) * CO_STG_BUF, ks + 2);

        unsigned actH = smu + CO_OFF_ACT + (ks & 1) * CO_ACT_BUF +
                        (ln15 * 136 + wp * 32 + hb8) * 2;
        unsigned Bh[8], A[4][4];
        ldm4t(Bh,     actH);
        ldm4t(Bh + 4, actH + 32);
        #pragma unroll
        for (int mt = 0; mt < 4; mt++)
            ldm4(A[mt], whB + mt * 6400 + ks * 32);
        #pragma unroll
        for (int mt = 0; mt < 4; mt++) {
            mma16816(acc[mt][0], A[mt][0], A[mt][1], A[mt][2], A[mt][3], Bh[0], Bh[1]);
            mma16816(acc[mt][1], A[mt][0], A[mt][1], A[mt][2], A[mt][3], Bh[2], Bh[3]);
            mma16816(acc[mt][2], A[mt][0], A[mt][1], A[mt][2], A[mt][3], Bh[4], Bh[5]);
            mma16816(acc[mt][3], A[mt][0], A[mt][1], A[mt][2], A[mt][3], Bh[6], Bh[7]);
        }

        if (ks + 1 < 12) {
            if (ks + 2 < 12) { asm volatile("cp.async.wait_group 1;\n"); }
            else             { asm volatile("cp.async.wait_group 0;\n"); }
            co_convert((const float*)(smc + CO_OFF_STG + ((ks + 1) & 1) * CO_STG_BUF),
                       (__half*)(smc + CO_OFF_ACT + ((ks + 1) & 1) * CO_ACT_BUF), t);
        }
    }

    // wait for attn, then fused combine + epilogue
    asm volatile("griddepcontrol.wait;" ::: "memory");
    __syncthreads();

    float* OS  = (float*)(smc + CO_OFF_STG);       // [64][36] combined O
    float* ES  = OS + 64 * 36;                     // [64][36] ef
    float* SS0 = ES + 64 * 36;                     // [32]
    float* SS1 = SS0 + 32;

    if (t < 32) {
        int nd = ndbase + t;
        float m0 = g_ml[(size_t)((0 * BATCH + b) * 2) * NDS + nd];
        float l0 = g_ml[(size_t)((0 * BATCH + b) * 2) * NDS + NDS + nd];
        float m1 = g_ml[(size_t)((1 * BATCH + b) * 2) * NDS + nd];
        float l1 = g_ml[(size_t)((1 * BATCH + b) * 2) * NDS + NDS + nd];
        float M  = fmaxf(m0, m1);
        float s0 = exp2f((m0 - M) * 1.44269504f);
        float s1 = exp2f((m1 - M) * 1.44269504f);
        float inv = 1.0f / (l0 * s0 + l1 * s1);
        SS0[t] = s0 * inv;
        SS1[t] = s1 * inv;
    }
    __syncthreads();

    {
        int o = t >> 1, c0 = (t & 1) << 4;
        const float* po0 = g_Op + (size_t)(b * 64 + o) * NDS + ndbase + c0;
        const float* po1 = g_Op + (size_t)(BATCH * CHN + b * 64 + o) * NDS + ndbase + c0;
        const float* pe  = g_efd + (size_t)(b * 64 + o) * NDS + ndbase + c0;
        #pragma unroll
        for (int j = 0; j < 4; j++) {
            float4 a0 = *(const float4*)(po0 + 4 * j);
            float4 a1 = *(const float4*)(po1 + 4 * j);
            int cc = c0 + 4 * j;
            float4 r;
            r.x = a0.x * SS0[cc]     + a1.x * SS1[cc];
            r.y = a0.y * SS0[cc + 1] + a1.y * SS1[cc + 1];
            r.z = a0.z * SS0[cc + 2] + a1.z * SS1[cc + 2];
            r.w = a0.w * SS0[cc + 3] + a1.w * SS1[cc + 3];
            *(float4*)&OS[o * 36 + cc] = r;
            *(float4*)&ES[o * 36 + cc] = *(const float4*)(pe + 4 * j);
        }
    }
    __syncthreads();

    float tg = THITA_F * __ldg(gamma);
    int g = lane >> 2, tig = lane & 3;
    #pragma unroll
    for (int mt = 0; mt < 4; mt++) {
        int o = mt * 16 + g;
        float bb0 = __ldg(&bias[o]), bb1 = __ldg(&bias[o + 8]);
        #pragma unroll
        for (int nb = 0; nb < 4; nb++) {
            int pxl = wp * 32 + nb * 8 + tig * 2;
            int ndc = pxl >> 2;
            float a0 = tg * OS[o * 36 + ndc];
            float a1 = tg * OS[(o + 8) * 36 + ndc];
            float2 r0 = make_float2(fmaxf(acc[mt][nb][0] + bb0, 0.0f) + a0,
                                    fmaxf(acc[mt][nb][1] + bb0, 0.0f) + a0);
            float2 r1 = make_float2(fmaxf(acc[mt][nb][2] + bb1, 0.0f) + a1,
                                    fmaxf(acc[mt][nb][3] + bb1, 0.0f) + a1);
            *(float2*)(out + (size_t)(b * 64 + o)     * HW + p0 + pxl) = r0;
            *(float2*)(out + (size_t)(b * 64 + o + 8) * HW + p0 + pxl) = r1;
        }
    }

    int xq = t & 31, oo = t >> 5;
    #pragma unroll
    for (int rep = 0; rep < 16; rep++) {
        int o = rep * 4 + oo;
        float v = ES[o * 36 + xq];
        *(float4*)(out + OUT2OFF + (size_t)(b * 64 + o) * HW + p0 + (xq << 2)) =
            make_float4(v, v, v, v);
    }
}

// ============================================================================
extern "C" void kernel_launch(void* const* d_in, const int* in_sizes, int n_in,
                              void* d_out, int out_size)
{
    const float* x1    = (const float*)d_in[0];
    const float* x2    = (const float*)d_in[1];
    const float* ev    = (const float*)d_in[2];
    const float* xw0   = (const float*)d_in[3];
    const float* xb0   = (const float*)d_in[4];
    const float* xw1   = (const float*)d_in[5];
    const float* xb1   = (const float*)d_in[6];
    const float* ew0   = (const float*)d_in[7];
    const float* eb0   = (const float*)d_in[8];
    const float* ew1   = (const float*)d_in[9];
    const float* eb1   = (const float*)d_in[10];
    const float* qw    = (const float*)d_in[11];
    const float* qb    = (const float*)d_in[12];
    const float* kw    = (const float*)d_in[13];
    const float* kb    = (const float*)d_in[14];
    const float* vw    = (const float*)d_in[15];
    const float* vb    = (const float*)d_in[16];
    const float* gamma = (const float*)d_in[17];
    float* out = (float*)d_out;

    cudaFuncSetAttribute(prep_kernel,
                         cudaFuncAttributeMaxDynamicSharedMemorySize, PREP_SMEM);
    cudaFuncSetAttribute(qkv_kernel,
                         cudaFuncAttributeMaxDynamicSharedMemorySize, QKV_SMEM);
    cudaFuncSetAttribute(attn_kernel,
                         cudaFuncAttributeMaxDynamicSharedMemorySize, ATTN_SMEM);
    cudaFuncSetAttribute(convout_kernel,
                         cudaFuncAttributeMaxDynamicSharedMemorySize, CONVOUT_SMEM);

    wconv_kernel<<<48, 256>>>(xw0);
    prep_kernel<<<dim3(NDS / 64, BATCH, 2), 128, PREP_SMEM>>>(
        x1, x2, ev, xw0, xb0, ew0, eb0, ew1, eb1);
    qkv_kernel<<<dim3(NDS / 64, BATCH), 128, QKV_SMEM>>>(
        xw1, xb1, qw, qb, kw, kb, vw, vb);
    attn_kernel<<<dim3(NDS / 64, BATCH, 2), 64, ATTN_SMEM>>>();

    // convout: PDL secondary — 50.7 KB CTA co-resides with attn(64,3);
    // epilogue (fused split-KV combine + add + ef_up) gated on wait.
    {
        cudaLaunchConfig_t cfg = {};
        cfg.gridDim = dim3(512, BATCH, 1);
        cfg.blockDim = dim3(128, 1, 1);
        cfg.dynamicSmemBytes = CONVOUT_SMEM;
        cfg.stream = 0;
        cudaLaunchAttribute attrs[1];
        attrs[0].id = cudaLaunchAttributeProgrammaticStreamSerialization;
        attrs[0].val.programmaticStreamSerializationAllowed = 1;
        cfg.attrs = attrs;
        cfg.numAttrs = 1;
        cudaLaunchKernelEx(&cfg, convout_kernel, x1, x2, xb0, gamma, out);
    }
}

// round 17
// speedup vs baseline: 1.2386x; 1.0723x over previous
#include <cuda_runtime.h>
#include <cuda_fp16.h>
#include <math.h>

#define BATCH 4
#define CHN 64
#define HW 65536        // 256*256
#define NDS 4096        // 64*64 downsampled pixels
#define THITA_F 1.0e-4f
#define OUT2OFF (BATCH * CHN * HW)

// ---------------- scratch (device globals) ----------------------------------
__device__ float  g_efd [BATCH * CHN * NDS];    // ef ds fp32 [b][c][n]
__device__ __half g_qh[BATCH * NDS * CHN];      // [b][n][d] f16
__device__ __half g_kh[BATCH * NDS * CHN];
__device__ __half g_vh[BATCH * NDS * CHN];
__device__ float  g_Op[2 * BATCH * CHN * NDS];  // split-KV partial O (unnormalized)
__device__ float  g_ml[2 * BATCH * 2 * NDS];    // split-KV per-row m and l
__device__ __half g_wh[64 * 200];               // conv0 weights f16 hi

// ============================================================================
// mma / ldmatrix helpers
// ============================================================================
__device__ __forceinline__ void mma16816(float* d,
    unsigned a0, unsigned a1, unsigned a2, unsigned a3,
    unsigned b0, unsigned b1)
{
    asm volatile(
        "mma.sync.aligned.m16n8k16.row.col.f32.f16.f16.f32 "
        "{%0,%1,%2,%3}, {%4,%5,%6,%7}, {%8,%9}, {%0,%1,%2,%3};\n"
        : "+f"(d[0]), "+f"(d[1]), "+f"(d[2]), "+f"(d[3])
        : "r"(a0), "r"(a1), "r"(a2), "r"(a3), "r"(b0), "r"(b1));
}
__device__ __forceinline__ void mma16816h(unsigned* d,
    unsigned a0, unsigned a1, unsigned a2, unsigned a3,
    unsigned b0, unsigned b1)
{
    asm volatile(
        "mma.sync.aligned.m16n8k16.row.col.f16.f16.f16.f16 "
        "{%0,%1}, {%2,%3,%4,%5}, {%6,%7}, {%0,%1};\n"
        : "+r"(d[0]), "+r"(d[1])
        : "r"(a0), "r"(a1), "r"(a2), "r"(a3), "r"(b0), "r"(b1));
}
__device__ __forceinline__ void ldm4(unsigned* r, unsigned a) {
    asm volatile("ldmatrix.sync.aligned.m8n8.x4.shared.b16 {%0,%1,%2,%3}, [%4];\n"
        : "=r"(r[0]), "=r"(r[1]), "=r"(r[2]), "=r"(r[3]) : "r"(a));
}
__device__ __forceinline__ void ldm4t(unsigned* r, unsigned a) {
    asm volatile("ldmatrix.sync.aligned.m8n8.x4.trans.shared.b16 {%0,%1,%2,%3}, [%4];\n"
        : "=r"(r[0]), "=r"(r[1]), "=r"(r[2]), "=r"(r[3]) : "r"(a));
}
__device__ __forceinline__ void cpasync16(unsigned dst, const void* src) {
    asm volatile("cp.async.cg.shared.global [%0], [%1], 16;\n"
        :: "r"(dst), "l"(src));
}
__device__ __forceinline__ unsigned packh2(float a, float b) {
    __half2 h = __floats2half2_rn(a, b);
    return *(unsigned*)&h;
}
__device__ __forceinline__ float sexp(float s, float c) {
    float t = fmaf(s, 12102203.16f, c);
    t = fmaxf(t, 0.0f);
    return __int_as_float(__float2int_rn(t));
}

// single-pass f16 GEMM
__device__ __forceinline__ void gemm1p(float acc[8][4], unsigned wb, int wstride,
                                       unsigned ab, int nks, int lane)
{
    int ln15 = lane & 15, hb8 = (lane >> 4) * 8;
    unsigned wl = wb + (ln15 * wstride + hb8) * 2;
    #pragma unroll
    for (int ks = 0; ks < nks; ks++) {
        unsigned al = ab + ((ks * 16 + ln15) * 72 + hb8) * 2;
        unsigned B[16], A[4];
        ldm4t(B,      al);
        ldm4t(B + 4,  al + 32);
        ldm4t(B + 8,  al + 64);
        ldm4t(B + 12, al + 96);
        ldm4(A, wl + ks * 32);
        #pragma unroll
        for (int nc = 0; nc < 8; nc++) {
            int ib = (nc >> 1) * 4 + (nc & 1) * 2;
            mma16816(acc[nc], A[0], A[1], A[2], A[3], B[ib], B[ib + 1]);
        }
    }
}

// 3-pass hi/lo GEMM (K=64)
__device__ __forceinline__ void gemm3p(float acc[8][4],
    unsigned wh, unsigned wlo, unsigned ah, unsigned alo, int lane)
{
    int ln15 = lane & 15, hb8 = (lane >> 4) * 8;
    unsigned wbh = wh  + (ln15 * 72 + hb8) * 2;
    unsigned wbl = wlo + (ln15 * 72 + hb8) * 2;
    #pragma unroll
    for (int ks = 0; ks < 4; ks++) {
        unsigned abh = ah  + ((ks * 16 + ln15) * 72 + hb8) * 2;
        unsigned abl = alo + ((ks * 16 + ln15) * 72 + hb8) * 2;
        unsigned Bh[16], Bl[16], Wf[4], Lf[4];
        ldm4t(Bh,      abh);
        ldm4t(Bh + 4,  abh + 32);
        ldm4t(Bh + 8,  abh + 64);
        ldm4t(Bh + 12, abh + 96);
        ldm4t(Bl,      abl);
        ldm4t(Bl + 4,  abl + 32);
        ldm4t(Bl + 8,  abl + 64);
        ldm4t(Bl + 12, abl + 96);
        ldm4(Wf, wbh + ks * 32);
        ldm4(Lf, wbl + ks * 32);
        #pragma unroll
        for (int nc = 0; nc < 8; nc++) {
            int ib = (nc >> 1) * 4 + (nc & 1) * 2;
            mma16816(acc[nc], Wf[0], Wf[1], Wf[2], Wf[3], Bh[ib], Bh[ib + 1]);
            mma16816(acc[nc], Wf[0], Wf[1], Wf[2], Wf[3], Bl[ib], Bl[ib + 1]);
            mma16816(acc[nc], Lf[0], Lf[1], Lf[2], Lf[3], Bh[ib], Bh[ib + 1]);
        }
    }
}

// ============================================================================
// K0: wconv — f16-hi conv0 weights for convout
// ============================================================================
__global__ void wconv_kernel(const float* __restrict__ w)
{
    int i = blockIdx.x * 256 + threadIdx.x;
    if (i < 12288) {
        int o = i / 192, c = i - o * 192;
        g_wh[o * 200 + c] = __float2half_rn(w[i]);
    }
}

// ============================================================================
// K1: front — fused prep+qkv, smem-resident intermediates.
//   z=0: conv0_ds -> t -> q, v (g_qh, g_vh)
//   z=1: ef chain (3-pass) -> g_efd; -> k (g_kh)
// 128 thr, 64 px/block, grid (64, BATCH, 2)
// ============================================================================
#define FRONT_SMEM 62464   // z0: W[64x200](25600) + ACT[192x72](27648) + TR[64x72](9216)

__global__ __launch_bounds__(128) void front_kernel(
    const float* __restrict__ x1, const float* __restrict__ x2,
    const float* __restrict__ ev,
    const float* __restrict__ xw0, const float* __restrict__ xb0,
    const float* __restrict__ xw1, const float* __restrict__ xb1,
    const float* __restrict__ qw,  const float* __restrict__ qb,
    const float* __restrict__ vw,  const float* __restrict__ vb,
    const float* __restrict__ ew0, const float* __restrict__ eb0,
    const float* __restrict__ ew1, const float* __restrict__ eb1,
    const float* __restrict__ kw,  const float* __restrict__ kb)
{
    extern __shared__ char smc[];
    unsigned smu = (unsigned)__cvta_generic_to_shared(smc);
    int t = threadIdx.x, lane = t & 31, w = t >> 5;
    int gid = lane >> 2, tig = lane & 3;
    int blk = blockIdx.x, b = blockIdx.y;
    int n0 = blk << 6;
    int o = (w << 4) + gid;

    float acc[8][4];
    #pragma unroll
    for (int nc = 0; nc < 8; nc++)
        #pragma unroll
        for (int q = 0; q < 4; q++) acc[nc][q] = 0.0f;

    if (blockIdx.z == 0) {
        // ------------------- chain: conv0_ds -> t -> q, v -------------------
        __half* W   = (__half*)smc;              // [64][200], later [64][72]
        __half* ACT = (__half*)(smc + 25600);    // [192][72]; later t [64][72]
        __half* TR  = (__half*)(smc + 53248);    // [64][72]
        unsigned oW = smu, oACT = smu + 25600, oTR = smu + 53248;

        for (int i = t; i < 12288; i += 128) {
            int oo = i / 192, c = i - oo * 192;
            W[oo * 200 + c] = __float2half_rn(xw0[i]);
        }
        for (int i = t; i < 12288; i += 128) {
            int c = i >> 6, x = i & 63;
            const float* s = (c < 128) ? x1 + (size_t)(b * 128 + c) * HW
                                       : x2 + (size_t)(b * 64 + c - 128) * HW;
            ACT[c * 72 + x] = __float2half_rn(s[(blk << 10) + (x << 2)]);
        }
        __syncthreads();

        // xds = relu(xw0 @ act + xb0) -> TR [c][px] f16
        gemm1p(acc, oW + (w * 16) * 400, 200, oACT, 12, lane);
        {
            float b0 = __ldg(&xb0[o]), b1 = __ldg(&xb0[o + 8]);
            #pragma unroll
            for (int nc = 0; nc < 8; nc++) {
                int px = nc * 8 + tig * 2;
                *(__half2*)&TR[o * 72 + px] = __floats2half2_rn(
                    fmaxf(acc[nc][0] + b0, 0.0f), fmaxf(acc[nc][1] + b0, 0.0f));
                *(__half2*)&TR[(o + 8) * 72 + px] = __floats2half2_rn(
                    fmaxf(acc[nc][2] + b1, 0.0f), fmaxf(acc[nc][3] + b1, 0.0f));
            }
        }
        __syncthreads();

        // t = relu(xw1 @ xds + xb1) -> ACT [c][px]
        for (int i = t; i < 4096; i += 128)
            W[(i >> 6) * 72 + (i & 63)] = __float2half_rn(xw1[i]);
        __syncthreads();
        #pragma unroll
        for (int nc = 0; nc < 8; nc++)
            #pragma unroll
            for (int q = 0; q < 4; q++) acc[nc][q] = 0.0f;
        gemm1p(acc, oW + (w * 16) * 144, 72, oTR, 4, lane);
        {
            float b0 = __ldg(&xb1[o]), b1 = __ldg(&xb1[o + 8]);
            #pragma unroll
            for (int nc = 0; nc < 8; nc++) {
                int px = nc * 8 + tig * 2;
                *(__half2*)&ACT[o * 72 + px] = __floats2half2_rn(
                    fmaxf(acc[nc][0] + b0, 0.0f), fmaxf(acc[nc][1] + b0, 0.0f));
                *(__half2*)&ACT[(o + 8) * 72 + px] = __floats2half2_rn(
                    fmaxf(acc[nc][2] + b1, 0.0f), fmaxf(acc[nc][3] + b1, 0.0f));
            }
        }
        __syncthreads();

        // q = relu(qw @ t + qb) -> transpose TR -> g_qh
        for (int i = t; i < 4096; i += 128)
            W[(i >> 6) * 72 + (i & 63)] = __float2half_rn(qw[i]);
        __syncthreads();
        #pragma unroll
        for (int nc = 0; nc < 8; nc++)
            #pragma unroll
            for (int q = 0; q < 4; q++) acc[nc][q] = 0.0f;
        gemm1p(acc, oW + (w * 16) * 144, 72, oACT, 4, lane);
        {
            float b0 = __ldg(&qb[o]), b1 = __ldg(&qb[o + 8]);
            #pragma unroll
            for (int nc = 0; nc < 8; nc++) {
                int px = nc * 8 + tig * 2;
                TR[px * 72 + o]           = __float2half_rn(fmaxf(acc[nc][0] + b0, 0.0f));
                TR[(px + 1) * 72 + o]     = __float2half_rn(fmaxf(acc[nc][1] + b0, 0.0f));
                TR[px * 72 + o + 8]       = __float2half_rn(fmaxf(acc[nc][2] + b1, 0.0f));
                TR[(px + 1) * 72 + o + 8] = __float2half_rn(fmaxf(acc[nc][3] + b1, 0.0f));
            }
        }
        __syncthreads();
        for (int i = t; i < 512; i += 128) {
            int row = i >> 3, off = i & 7;
            *(uint4*)&g_qh[((size_t)b * NDS + n0 + row) * 64 + off * 8] =
                *(uint4*)&TR[row * 72 + off * 8];
        }

        // v = relu(vw @ t + vb) -> transpose TR -> g_vh
        for (int i = t; i < 4096; i += 128)
            W[(i >> 6) * 72 + (i & 63)] = __float2half_rn(vw[i]);
        __syncthreads();
        #pragma unroll
        for (int nc = 0; nc < 8; nc++)
            #pragma unroll
            for (int q = 0; q < 4; q++) acc[nc][q] = 0.0f;
        gemm1p(acc, oW + (w * 16) * 144, 72, oACT, 4, lane);
        {
            float b0 = __ldg(&vb[o]), b1 = __ldg(&vb[o + 8]);
            #pragma unroll
            for (int nc = 0; nc < 8; nc++) {
                int px = nc * 8 + tig * 2;
                TR[px * 72 + o]           = __float2half_rn(fmaxf(acc[nc][0] + b0, 0.0f));
                TR[(px + 1) * 72 + o]     = __float2half_rn(fmaxf(acc[nc][1] + b0, 0.0f));
                TR[px * 72 + o + 8]       = __float2half_rn(fmaxf(acc[nc][2] + b1, 0.0f));
                TR[(px + 1) * 72 + o + 8] = __float2half_rn(fmaxf(acc[nc][3] + b1, 0.0f));
            }
        }
        __syncthreads();
        for (int i = t; i < 512; i += 128) {
            int row = i >> 3, off = i & 7;
            *(uint4*)&g_vh[((size_t)b * NDS + n0 + row) * 64 + off * 8] =
                *(uint4*)&TR[row * 72 + off * 8];
        }
    } else {
        // ------------------- chain: ef (3-pass x2) -> k -------------------
        __half* Wh = (__half*)smc;
        __half* Wl = Wh + 64 * 72;
        __half* Ah = Wl + 64 * 72;
        __half* Al = Ah + 64 * 72;
        __half* TR = Al + 64 * 72;
        unsigned oWh = smu, oWl = smu + 9216, oAh = smu + 18432, oAl = smu + 27648;

        for (int i = t; i < 4096; i += 128) {
            float v = ew0[i];
            __half h = __float2half_rn(v);
            int oo = i >> 6, c = i & 63;
            Wh[oo * 72 + c] = h;
            Wl[oo * 72 + c] = __float2half_rn(v - __half2float(h));
        }
        for (int i = t; i < 4096; i += 128) {
            int c = i >> 6, x = i & 63;
            float v = ev[(size_t)(b * 64 + c) * HW + (blk << 10) + (x << 2)];
            __half h = __float2half_rn(v);
            Ah[c * 72 + x] = h;
            Al[c * 72 + x] = __float2half_rn(v - __half2float(h));
        }
        __syncthreads();

        gemm3p(acc, oWh + (w * 16) * 144, oWl + (w * 16) * 144, oAh, oAl, lane);
        __syncthreads();

        {
            float b0 = __ldg(&eb0[o]), b1 = __ldg(&eb0[o + 8]);
            #pragma unroll
            for (int nc = 0; nc < 8; nc++) {
                int px = nc * 8 + tig * 2;
                float t0 = fmaxf(acc[nc][0] + b0, 0.0f);
                float t1 = fmaxf(acc[nc][1] + b0, 0.0f);
                float t2 = fmaxf(acc[nc][2] + b1, 0.0f);
                float t3 = fmaxf(acc[nc][3] + b1, 0.0f);
                __half h0 = __float2half_rn(t0), h1 = __float2half_rn(t1);
                __half h2 = __float2half_rn(t2), h3 = __float2half_rn(t3);
                *(__half2*)&Ah[o * 72 + px] = __halves2half2(h0, h1);
                *(__half2*)&Al[o * 72 + px] = __floats2half2_rn(
                    t0 - __half2float(h0), t1 - __half2float(h1));
                *(__half2*)&Ah[(o + 8) * 72 + px] = __halves2half2(h2, h3);
                *(__half2*)&Al[(o + 8) * 72 + px] = __floats2half2_rn(
                    t2 - __half2float(h2), t3 - __half2float(h3));
            }
        }
        for (int i = t; i < 4096; i += 128) {
            float v = ew1[i];
            __half h = __float2half_rn(v);
            int oo = i >> 6, c = i & 63;
            Wh[oo * 72 + c] = h;
            Wl[oo * 72 + c] = __float2half_rn(v - __half2float(h));
        }
        __syncthreads();

        #pragma unroll
        for (int nc = 0; nc < 8; nc++)
            #pragma unroll
            for (int q = 0; q < 4; q++) acc[nc][q] = 0.0f;
        gemm3p(acc, oWh + (w * 16) * 144, oWl + (w * 16) * 144, oAh, oAl, lane);
        __syncthreads();   // all Ah/Al reads done before ef overwrite

        // write ef: g_efd (f32, feeds ef_up) + Ah (f16, feeds k conv)
        {
            float b0 = __ldg(&eb1[o]), b1 = __ldg(&eb1[o + 8]);
            #pragma unroll
            for (int nc = 0; nc < 8; nc++) {
                int px = nc * 8 + tig * 2;
                int n = n0 + px;
                float r0 = fmaxf(acc[nc][0] + b0, 0.0f);
                float r1 = fmaxf(acc[nc][1] + b0, 0.0f);
                float r2 = fmaxf(acc[nc][2] + b1, 0.0f);
                float r3 = fmaxf(acc[nc][3] + b1, 0.0f);
                *(float2*)&g_efd[(size_t)(b * 64 + o) * NDS + n]     = make_float2(r0, r1);
                *(float2*)&g_efd[(size_t)(b * 64 + o + 8) * NDS + n] = make_float2(r2, r3);
                *(__half2*)&Ah[o * 72 + px]       = __floats2half2_rn(r0, r1);
                *(__half2*)&Ah[(o + 8) * 72 + px] = __floats2half2_rn(r2, r3);
            }
        }
        // k weights into Wh (stride 72)
        for (int i = t; i < 4096; i += 128)
            Wh[(i >> 6) * 72 + (i & 63)] = __float2half_rn(kw[i]);
        __syncthreads();

        // k = relu(kw @ ef + kb) -> transpose TR -> g_kh
        #pragma unroll
        for (int nc = 0; nc < 8; nc++)
            #pragma unroll
            for (int q = 0; q < 4; q++) acc[nc][q] = 0.0f;
        gemm1p(acc, oWh + (w * 16) * 144, 72, oAh, 4, lane);
        {
            float b0 = __ldg(&kb[o]), b1 = __ldg(&kb[o + 8]);
            #pragma unroll
            for (int nc = 0; nc < 8; nc++) {
                int px = nc * 8 + tig * 2;
                TR[px * 72 + o]           = __float2half_rn(fmaxf(acc[nc][0] + b0, 0.0f));
                TR[(px + 1) * 72 + o]     = __float2half_rn(fmaxf(acc[nc][1] + b0, 0.0f));
                TR[px * 72 + o + 8]       = __float2half_rn(fmaxf(acc[nc][2] + b1, 0.0f));
                TR[(px + 1) * 72 + o + 8] = __float2half_rn(fmaxf(acc[nc][3] + b1, 0.0f));
            }
        }
        __syncthreads();
        for (int i = t; i < 512; i += 128) {
            int row = i >> 3, off = i & 7;
            *(uint4*)&g_kh[((size_t)b * NDS + n0 + row) * 64 + off * 8] =
                *(uint4*)&TR[row * 72 + off * 8];
        }
    }
}

// ============================================================================
// K2: flash attention — split-KV x2, 64-thr CTAs, f16 PV accumulators.
// (64,3): 138 KB so a 50.7 KB convout CTA co-resides. (round-16 verbatim)
// ============================================================================
#define SM_STRIDE 72
#define ATTN_SMEM ((64 * SM_STRIDE + 4 * 64 * SM_STRIDE) * 2)   // 46080

__global__ __launch_bounds__(64, 3) void attn_kernel()
{
    extern __shared__ __half smh[];
    __half* qs  = smh;
    __half* ks0 = smh + 64 * SM_STRIDE;
    __half* vs0 = ks0 + 2 * 64 * SM_STRIDE;

    int tid  = threadIdx.x;
    int lane = tid & 31, w = tid >> 5;
    int gid  = lane >> 2, tig = lane & 3;
    int b    = blockIdx.y;
    int m0   = blockIdx.x << 6;
    int split = blockIdx.z;
    int it0  = split << 5;

    const __half* qg = g_qh + (size_t)b * NDS * 64;
    const __half* kg = g_kh + (size_t)b * NDS * 64;
    const __half* vg = g_vh + (size_t)b * NDS * 64;

    unsigned qs_base = (unsigned)__cvta_generic_to_shared(qs);
    unsigned ks_base = (unsigned)__cvta_generic_to_shared(ks0);
    unsigned vs_base = (unsigned)__cvta_generic_to_shared(vs0);

    #pragma unroll
    for (int rep = 0; rep < 8; rep++) {
        int c = tid + rep * 64;
        int row = c >> 3, off = c & 7;
        cpasync16(ks_base + (row * SM_STRIDE + off * 8) * 2,
                  kg + (size_t)(it0 * 64 + row) * 64 + off * 8);
        cpasync16(vs_base + (row * SM_STRIDE + off * 8) * 2,
                  vg + (size_t)(it0 * 64 + row) * 64 + off * 8);
    }
    asm volatile("cp.async.commit_group;\n");

    asm volatile("griddepcontrol.launch_dependents;" ::: "memory");

    for (int c = tid; c < 512; c += 64) {
        int row = c >> 3, off = c & 7;
        *(uint4*)(qs + row * SM_STRIDE + off * 8) =
            *(const uint4*)(qg + (size_t)(m0 + row) * 64 + off * 8);
    }
    asm volatile("cp.async.wait_group 0;\n");
    __syncthreads();

    unsigned qa[2][4][4];
    #pragma unroll
    for (int s = 0; s < 2; s++) {
        int row = (w << 5) + (s << 4) + (lane & 15);
        #pragma unroll
        for (int kc = 0; kc < 4; kc++) {
            int dof = kc * 16 + (lane >> 4) * 8;
            ldm4(qa[s][kc], qs_base + (row * SM_STRIDE + dof) * 2);
        }
    }

    unsigned Ofh[2][8][2];
    #pragma unroll
    for (int s = 0; s < 2; s++)
        #pragma unroll
        for (int dc = 0; dc < 8; dc++) {
            Ofh[s][dc][0] = 0u; Ofh[s][dc][1] = 0u;
        }
    float mrow[2][2], lrow[2][2];
    #pragma unroll
    for (int s = 0; s < 2; s++) {
        mrow[s][0] = -1e30f; mrow[s][1] = -1e30f;
        lrow[s][0] = 0.0f;   lrow[s][1] = 0.0f;
    }
    const unsigned ONES = 0x3C003C00u;

    for (int itr = 0; itr < 32; itr++) {
        int bf = itr & 1;
        unsigned ksb = ks_base + bf * 64 * SM_STRIDE * 2;
        unsigned vsb = vs_base + bf * 64 * SM_STRIDE * 2;

        if (itr + 1 < 32) {
            int n0n = (it0 + itr + 1) << 6;
            int nb  = (itr + 1) & 1;
            #pragma unroll
            for (int rep = 0; rep < 8; rep++) {
                int c = tid + rep * 64;
                int row = c >> 3, off = c & 7;
                cpasync16(ks_base + (nb * 64 * SM_STRIDE + row * SM_STRIDE + off * 8) * 2,
                          kg + (size_t)(n0n + row) * 64 + off * 8);
                cpasync16(vs_base + (nb * 64 * SM_STRIDE + row * SM_STRIDE + off * 8) * 2,
                          vg + (size_t)(n0n + row) * 64 + off * 8);
            }
            asm volatile("cp.async.commit_group;\n");
        }

        float S[2][8][4];
        #pragma unroll
        for (int nc = 0; nc < 8; nc++) {
            unsigned kb[8];
            int krow = nc * 8 + (lane & 7);
            int kd   = (lane >> 3) * 8;
            ldm4(kb,     ksb + (krow * SM_STRIDE + kd) * 2);
            ldm4(kb + 4, ksb + (krow * SM_STRIDE + 32 + kd) * 2);
            #pragma unroll
            for (int s = 0; s < 2; s++) {
                #pragma unroll
                for (int q = 0; q < 4; q++) S[s][nc][q] = 0.0f;
                mma16816(S[s][nc], qa[s][0][0], qa[s][0][1], qa[s][0][2], qa[s][0][3], kb[0], kb[1]);
                mma16816(S[s][nc], qa[s][1][0], qa[s][1][1], qa[s][1][2], qa[s][1][3], kb[2], kb[3]);
                mma16816(S[s][nc], qa[s][2][0], qa[s][2][1], qa[s][2][2], qa[s][2][3], kb[4], kb[5]);
                mma16816(S[s][nc], qa[s][3][0], qa[s][3][1], qa[s][3][2], qa[s][3][3], kb[6], kb[7]);
            }
        }

        unsigned P[2][4][4];
        #pragma unroll
        for (int s = 0; s < 2; s++) {
            float tm0 = fmaxf(S[s][0][0], S[s][0][1]);
            float tm1 = fmaxf(S[s][0][2], S[s][0][3]);
            #pragma unroll
            for (int nc = 1; nc < 8; nc++) {
                tm0 = fmaxf(tm0, fmaxf(S[s][nc][0], S[s][nc][1]));
                tm1 = fmaxf(tm1, fmaxf(S[s][nc][2], S[s][nc][3]));
            }
            tm0 = fmaxf(tm0, __shfl_xor_sync(0xffffffffu, tm0, 1));
            tm0 = fmaxf(tm0, __shfl_xor_sync(0xffffffffu, tm0, 2));
            tm1 = fmaxf(tm1, __shfl_xor_sync(0xffffffffu, tm1, 1));
            tm1 = fmaxf(tm1, __shfl_xor_sync(0xffffffffu, tm1, 2));
            float nm0 = fmaxf(mrow[s][0], tm0), nm1 = fmaxf(mrow[s][1], tm1);
            float sc0 = exp2f((mrow[s][0] - nm0) * 1.44269504f);
            float sc1 = exp2f((mrow[s][1] - nm1) * 1.44269504f);
            mrow[s][0] = nm0; mrow[s][1] = nm1;
            float c0 = 1064866805.0f - nm0 * 12102203.16f;
            float c1 = 1064866805.0f - nm1 * 12102203.16f;

            #pragma unroll
            for (int jc = 0; jc < 4; jc++) {
                P[s][jc][0] = packh2(sexp(S[s][2*jc][0],   c0), sexp(S[s][2*jc][1],   c0));
                P[s][jc][1] = packh2(sexp(S[s][2*jc][2],   c1), sexp(S[s][2*jc][3],   c1));
                P[s][jc][2] = packh2(sexp(S[s][2*jc+1][0], c0), sexp(S[s][2*jc+1][1], c0));
                P[s][jc][3] = packh2(sexp(S[s][2*jc+1][2], c1), sexp(S[s][2*jc+1][3], c1));
            }

            unsigned lf[2] = {0u, 0u};
            #pragma unroll
            for (int jc = 0; jc < 4; jc++)
                mma16816h(lf, P[s][jc][0], P[s][jc][1], P[s][jc][2], P[s][jc][3], ONES, ONES);
            __half2 l0h = *(__half2*)&lf[0];
            __half2 l1h = *(__half2*)&lf[1];
            lrow[s][0] = lrow[s][0] * sc0 + __low2float(l0h);
            lrow[s][1] = lrow[s][1] * sc1 + __low2float(l1h);

            __half2 hs0 = __float2half2_rn(sc0);
            __half2 hs1 = __float2half2_rn(sc1);
            #pragma unroll
            for (int dc = 0; dc < 8; dc++) {
                __half2 a0 = *(__half2*)&Ofh[s][dc][0];
                __half2 a1 = *(__half2*)&Ofh[s][dc][1];
                a0 = __hmul2(a0, hs0);
                a1 = __hmul2(a1, hs1);
                Ofh[s][dc][0] = *(unsigned*)&a0;
                Ofh[s][dc][1] = *(unsigned*)&a1;
            }
        }

        #pragma unroll
        for (int jc = 0; jc < 4; jc++) {
            int vrow = jc * 16 + (lane & 15);
            int vcb  = (lane >> 4) * 8;
            #pragma unroll
            for (int dcp = 0; dcp < 4; dcp++) {
                unsigned vb[4];
                ldm4t(vb, vsb + (vrow * SM_STRIDE + dcp * 16 + vcb) * 2);
                #pragma unroll
                for (int s = 0; s < 2; s++) {
                    mma16816h(Ofh[s][2*dcp],     P[s][jc][0], P[s][jc][1], P[s][jc][2], P[s][jc][3], vb[0], vb[1]);
                    mma16816h(Ofh[s][2*dcp + 1], P[s][jc][0], P[s][jc][1], P[s][jc][2], P[s][jc][3], vb[2], vb[3]);
                }
            }
        }

        if (itr + 1 < 32) {
            asm volatile("cp.async.wait_group 0;\n");
            __syncthreads();
        }
    }

    float* Op = g_Op + (size_t)split * BATCH * CHN * NDS;
    #pragma unroll
    for (int s = 0; s < 2; s++) {
        int m = m0 + (w << 5) + (s << 4) + gid;
        #pragma unroll
        for (int dc = 0; dc < 8; dc++) {
            int d0 = dc * 8 + tig * 2;
            __half2 v0 = *(__half2*)&Ofh[s][dc][0];
            __half2 v1 = *(__half2*)&Ofh[s][dc][1];
            Op[(b * 64 + d0)     * NDS + m]     = __low2float(v0);
            Op[(b * 64 + d0 + 1) * NDS + m]     = __high2float(v0);
            Op[(b * 64 + d0)     * NDS + m + 8] = __low2float(v1);
            Op[(b * 64 + d0 + 1) * NDS + m + 8] = __high2float(v1);
        }
        if (tig == 0) {
            float* ml = g_ml + (size_t)((split * BATCH + b) * 2) * NDS;
            ml[m]           = mrow[s][0];
            ml[m + 8]       = mrow[s][1];
            ml[NDS + m]     = lrow[s][0];
            ml[NDS + m + 8] = lrow[s][1];
        }
    }
}

// ============================================================================
// K3: convout — single weight pass, 50.7 KB smem (round-16 verbatim).
// ============================================================================
#define CO_OFF_WH  0
#define CO_OFF_STG 25600
#define CO_STG_BUF 8192
#define CO_OFF_ACT 41984
#define CO_ACT_BUF 4352
#define CONVOUT_SMEM 50688

__device__ __forceinline__ void co_issue_stage(
    const float* __restrict__ x1, const float* __restrict__ x2,
    int b, int p0, int t, unsigned dstbase, int ks)
{
    #pragma unroll
    for (int rep = 0; rep < 4; rep++) {
        int i = t + rep * 128;
        int row = i >> 5, off = i & 31;
        int c = ks * 16 + row;
        const float* src = (c < 128) ? x1 + (size_t)(b * 128 + c) * HW
                                     : x2 + (size_t)(b * 64 + c - 128) * HW;
        cpasync16(dstbase + row * 512 + off * 16, src + p0 + off * 4);
    }
    asm volatile("cp.async.commit_group;\n");
}

__device__ __forceinline__ void co_convert(const float* stg, __half* AH, int t)
{
    #pragma unroll
    for (int ch = 0; ch < 4; ch++) {
        int i = ch * 512 + t * 4;
        int row = i >> 7, col = i & 127;
        float4 v = *(const float4*)(stg + i);
        __half2 h0 = __floats2half2_rn(v.x, v.y);
        __half2 h1 = __floats2half2_rn(v.z, v.w);
        uint2 u;
        u.x = *(unsigned*)&h0;
        u.y = *(unsigned*)&h1;
        *(uint2*)&AH[row * 136 + col] = u;
    }
}

__global__ __launch_bounds__(128, 4) void convout_kernel(
    const float* __restrict__ x1, const float* __restrict__ x2,
    const float* __restrict__ bias,
    const float* __restrict__ gamma, float* __restrict__ out)
{
    extern __shared__ char smc[];
    unsigned smu = (unsigned)__cvta_generic_to_shared(smc);

    int t = threadIdx.x;
    int lane = t & 31, wp = t >> 5;
    int ln15 = lane & 15, hb8 = (lane >> 4) * 8;
    int bx = blockIdx.x, b = blockIdx.y;
    int y = bx >> 1, xh = bx & 1;
    int p0 = (y << 8) + (xh << 7);
    int ndbase = ((y >> 2) << 6) + (xh << 5);

    #pragma unroll
    for (int rep = 0; rep < 13; rep++) {
        int i = t + rep * 128;
        if (i < 1600)
            cpasync16(smu + CO_OFF_WH + i * 16, (const char*)g_wh + i * 16);
    }
    co_issue_stage(x1, x2, b, p0, t, smu + CO_OFF_STG, 0);
    co_issue_stage(x1, x2, b, p0, t, smu + CO_OFF_STG + CO_STG_BUF, 1);

    asm volatile("cp.async.wait_group 1;\n");
    __syncthreads();
    co_convert((const float*)(smc + CO_OFF_STG), (__half*)(smc + CO_OFF_ACT), t);

    float acc[4][4][4];
    #pragma unroll
    for (int mt = 0; mt < 4; mt++)
        #pragma unroll
        for (int nb = 0; nb < 4; nb++)
            #pragma unroll
            for (int q = 0; q < 4; q++) acc[mt][nb][q] = 0.0f;

    unsigned whB = smu + CO_OFF_WH + (ln15 * 200 + hb8) * 2;

    #pragma unroll 1
    for (int ks = 0; ks < 12; ks++) {
        __syncthreads();
        if (ks + 2 < 12)
            co_issue_stage(x1, x2, b, p0, t,
                           smu + CO_OFF_STG + (ks & 1) * CO_STG_BUF, ks + 2);

        unsigned actH = smu + CO_OFF_ACT + (ks & 1) * CO_ACT_BUF +
                        (ln15 * 136 + wp * 32 + hb8) * 2;
        unsigned Bh[8], A[4][4];
        ldm4t(Bh,     actH);
        ldm4t(Bh + 4, actH + 32);
        #pragma unroll
        for (int mt = 0; mt < 4; mt++)
            ldm4(A[mt], whB + mt * 6400 + ks * 32);
        #pragma unroll
        for (int mt = 0; mt < 4; mt++) {
            mma16816(acc[mt][0], A[mt][0], A[mt][1], A[mt][2], A[mt][3], Bh[0], Bh[1]);
            mma16816(acc[mt][1], A[mt][0], A[mt][1], A[mt][2], A[mt][3], Bh[2], Bh[3]);
            mma16816(acc[mt][2], A[mt][0], A[mt][1], A[mt][2], A[mt][3], Bh[4], Bh[5]);
            mma16816(acc[mt][3], A[mt][0], A[mt][1], A[mt][2], A[mt][3], Bh[6], Bh[7]);
        }

        if (ks + 1 < 12) {
            if (ks + 2 < 12) { asm volatile("cp.async.wait_group 1;\n"); }
            else             { asm volatile("cp.async.wait_group 0;\n"); }
            co_convert((const float*)(smc + CO_OFF_STG + ((ks + 1) & 1) * CO_STG_BUF),
                       (__half*)(smc + CO_OFF_ACT + ((ks + 1) & 1) * CO_ACT_BUF), t);
        }
    }

    asm volatile("griddepcontrol.wait;" ::: "memory");
    __syncthreads();

    float* OS  = (float*)(smc + CO_OFF_STG);
    float* ES  = OS + 64 * 36;
    float* SS0 = ES + 64 * 36;
    float* SS1 = SS0 + 32;

    if (t < 32) {
        int nd = ndbase + t;
        float m0 = g_ml[(size_t)((0 * BATCH + b) * 2) * NDS + nd];
        float l0 = g_ml[(size_t)((0 * BATCH + b) * 2) * NDS + NDS + nd];
        float m1 = g_ml[(size_t)((1 * BATCH + b) * 2) * NDS + nd];
        float l1 = g_ml[(size_t)((1 * BATCH + b) * 2) * NDS + NDS + nd];
        float M  = fmaxf(m0, m1);
        float s0 = exp2f((m0 - M) * 1.44269504f);
        float s1 = exp2f((m1 - M) * 1.44269504f);
        float inv = 1.0f / (l0 * s0 + l1 * s1);
        SS0[t] = s0 * inv;
        SS1[t] = s1 * inv;
    }
    __syncthreads();

    {
        int o = t >> 1, c0 = (t & 1) << 4;
        const float* po0 = g_Op + (size_t)(b * 64 + o) * NDS + ndbase + c0;
        const float* po1 = g_Op + (size_t)(BATCH * CHN + b * 64 + o) * NDS + ndbase + c0;
        const float* pe  = g_efd + (size_t)(b * 64 + o) * NDS + ndbase + c0;
        #pragma unroll
        for (int j = 0; j < 4; j++) {
            float4 a0 = *(const float4*)(po0 + 4 * j);
            float4 a1 = *(const float4*)(po1 + 4 * j);
            int cc = c0 + 4 * j;
            float4 r;
            r.x = a0.x * SS0[cc]     + a1.x * SS1[cc];
            r.y = a0.y * SS0[cc + 1] + a1.y * SS1[cc + 1];
            r.z = a0.z * SS0[cc + 2] + a1.z * SS1[cc + 2];
            r.w = a0.w * SS0[cc + 3] + a1.w * SS1[cc + 3];
            *(float4*)&OS[o * 36 + cc] = r;
            *(float4*)&ES[o * 36 + cc] = *(const float4*)(pe + 4 * j);
        }
    }
    __syncthreads();

    float tg = THITA_F * __ldg(gamma);
    int g = lane >> 2, tig = lane & 3;
    #pragma unroll
    for (int mt = 0; mt < 4; mt++) {
        int o = mt * 16 + g;
        float bb0 = __ldg(&bias[o]), bb1 = __ldg(&bias[o + 8]);
        #pragma unroll
        for (int nb = 0; nb < 4; nb++) {
            int pxl = wp * 32 + nb * 8 + tig * 2;
            int ndc = pxl >> 2;
            float a0 = tg * OS[o * 36 + ndc];
            float a1 = tg * OS[(o + 8) * 36 + ndc];
            float2 r0 = make_float2(fmaxf(acc[mt][nb][0] + bb0, 0.0f) + a0,
                                    fmaxf(acc[mt][nb][1] + bb0, 0.0f) + a0);
            float2 r1 = make_float2(fmaxf(acc[mt][nb][2] + bb1, 0.0f) + a1,
                                    fmaxf(acc[mt][nb][3] + bb1, 0.0f) + a1);
            *(float2*)(out + (size_t)(b * 64 + o)     * HW + p0 + pxl) = r0;
            *(float2*)(out + (size_t)(b * 64 + o + 8) * HW + p0 + pxl) = r1;
        }
    }

    int xq = t & 31, oo = t >> 5;
    #pragma unroll
    for (int rep = 0; rep < 16; rep++) {
        int o = rep * 4 + oo;
        float v = ES[o * 36 + xq];
        *(float4*)(out + OUT2OFF + (size_t)(b * 64 + o) * HW + p0 + (xq << 2)) =
            make_float4(v, v, v, v);
    }
}

// ============================================================================
extern "C" void kernel_launch(void* const* d_in, const int* in_sizes, int n_in,
                              void* d_out, int out_size)
{
    const float* x1    = (const float*)d_in[0];
    const float* x2    = (const float*)d_in[1];
    const float* ev    = (const float*)d_in[2];
    const float* xw0   = (const float*)d_in[3];
    const float* xb0   = (const float*)d_in[4];
    const float* xw1   = (const float*)d_in[5];
    const float* xb1   = (const float*)d_in[6];
    const float* ew0   = (const float*)d_in[7];
    const float* eb0   = (const float*)d_in[8];
    const float* ew1   = (const float*)d_in[9];
    const float* eb1   = (const float*)d_in[10];
    const float* qw    = (const float*)d_in[11];
    const float* qb    = (const float*)d_in[12];
    const float* kw    = (const float*)d_in[13];
    const float* kb    = (const float*)d_in[14];
    const float* vw    = (const float*)d_in[15];
    const float* vb    = (const float*)d_in[16];
    const float* gamma = (const float*)d_in[17];
    float* out = (float*)d_out;

    cudaFuncSetAttribute(front_kernel,
                         cudaFuncAttributeMaxDynamicSharedMemorySize, FRONT_SMEM);
    cudaFuncSetAttribute(attn_kernel,
                         cudaFuncAttributeMaxDynamicSharedMemorySize, ATTN_SMEM);
    cudaFuncSetAttribute(convout_kernel,
                         cudaFuncAttributeMaxDynamicSharedMemorySize, CONVOUT_SMEM);

    wconv_kernel<<<48, 256>>>(xw0);
    front_kernel<<<dim3(NDS / 64, BATCH, 2), 128, FRONT_SMEM>>>(
        x1, x2, ev, xw0, xb0, xw1, xb1, qw, qb, vw, vb,
        ew0, eb0, ew1, eb1, kw, kb);
    attn_kernel<<<dim3(NDS / 64, BATCH, 2), 64, ATTN_SMEM>>>();

    // convout: PDL secondary — 50.7 KB CTA co-resides with attn(64,3);
    // epilogue (fused split-KV combine + add + ef_up) gated on wait.
    {
        cudaLaunchConfig_t cfg = {};
        cfg.gridDim = dim3(512, BATCH, 1);
        cfg.blockDim = dim3(128, 1, 1);
        cfg.dynamicSmemBytes = CONVOUT_SMEM;
        cfg.stream = 0;
        cudaLaunchAttribute attrs[1];
        attrs[0].id = cudaLaunchAttributeProgrammaticStreamSerialization;
        attrs[0].val.programmaticStreamSerializationAllowed = 1;
        cfg.attrs = attrs;
        cfg.numAttrs = 1;
        cudaLaunchKernelEx(&cfg, convout_kernel, x1, x2, xb0, gamma, out);
    }
}